// round 12
// baseline (speedup 1.0000x reference)
#include <cuda_runtime.h>
#include <cuda_fp16.h>
#include <cstdint>

#define NN   100000
#define HD   64
#define EMAX 3200000
#define NBLK ((NN + 1023) / 1024)   // 98
#define MBLK ((NN + 63) / 64)       // 1563

// ---- scratch (device globals; no allocation allowed) ----
__device__ __align__(16) __half g_hhi[NN * HD];   // h hi plane (12.8 MB) — also gather table
__device__ __align__(16) __half g_hlo[NN * HD];   // h lo (residual) plane (12.8 MB)
__device__ __align__(16) __half g_agghi[NN * HD]; // aggregated neighbors, hi only (12.8 MB)
__device__ int   g_cnt[NN];
__device__ float g_inv[NN];
__device__ int   g_rowptr[NN + 1];
__device__ int   g_fill[NN];
__device__ int   g_esrc[EMAX];
__device__ int   g_is64;
__device__ int   g_bsum[NBLK];
__device__ int   g_boff[NBLK];

// ---------------------------------------------------------------- fp16 split mma helpers
__device__ __forceinline__ void mma_f16(float* d, const uint32_t* a, const uint32_t* b) {
    asm volatile(
        "mma.sync.aligned.m16n8k16.row.col.f32.f16.f16.f32 "
        "{%0,%1,%2,%3}, {%4,%5,%6,%7}, {%8,%9}, {%0,%1,%2,%3};\n"
        : "+f"(d[0]), "+f"(d[1]), "+f"(d[2]), "+f"(d[3])
        : "r"(a[0]), "r"(a[1]), "r"(a[2]), "r"(a[3]), "r"(b[0]), "r"(b[1]));
}
__device__ __forceinline__ void split2(float a, float b, __half2& hi, __half2& lo) {
    __half ha = __float2half_rn(a), hb = __float2half_rn(b);
    hi = __halves2half2(ha, hb);
    lo = __floats2half2_rn(a - __half2float(ha), b - __half2float(hb));
}

// ---------------------------------------------------------------- dtype probe
__global__ void detect_kernel(const int* __restrict__ ei32) {
    if (threadIdx.x == 0 && blockIdx.x == 0) {
        int nz = 0;
        for (int k = 0; k < 64; k++) nz |= ei32[2 * k + 1];
        g_is64 = (nz == 0) ? 1 : 0;
    }
}
__device__ __forceinline__ int load_idx(const void* ei, size_t pos) {
    if (g_is64) return (int)((const long long*)ei)[pos];
    return ((const int*)ei)[pos];
}

// ---------------------------------------------------------------- zero / degree
__global__ void zero_kernel() {
    int i = blockIdx.x * blockDim.x + threadIdx.x;
    if (i < NN) { g_cnt[i] = 0; g_fill[i] = 0; }
}
__global__ void degree_kernel(const void* __restrict__ ei, int E) {
    int e = blockIdx.x * blockDim.x + threadIdx.x;
    if (e < E) {
        int d = load_idx(ei, (size_t)E + e);
        if ((unsigned)d < NN) atomicAdd(&g_cnt[d], 1);
    }
}

// ---------------------------------------------------------------- hierarchical scan
__global__ __launch_bounds__(1024) void scan_partial_kernel() {
    __shared__ int s[1024];
    int tid = threadIdx.x, b = blockIdx.x;
    int i = b * 1024 + tid;
    int v = (i < NN) ? g_cnt[i] : 0;
    if (i < NN) g_inv[i] = 1.0f / fmaxf((float)v, 1.0f);
    s[tid] = v;
    __syncthreads();
#pragma unroll
    for (int off = 1; off < 1024; off <<= 1) {
        int t = (tid >= off) ? s[tid - off] : 0;
        __syncthreads();
        s[tid] += t;
        __syncthreads();
    }
    if (i < NN) g_rowptr[i + 1] = s[tid];
    if (tid == 1023) g_bsum[b] = s[1023];
    if (i == 0) g_rowptr[0] = 0;
}
__global__ void scan_bsum_kernel() {
    __shared__ int s[128];
    int tid = threadIdx.x;
    int v = (tid < NBLK) ? g_bsum[tid] : 0;
    s[tid] = v;
    __syncthreads();
#pragma unroll
    for (int off = 1; off < 128; off <<= 1) {
        int t = (tid >= off) ? s[tid - off] : 0;
        __syncthreads();
        s[tid] += t;
        __syncthreads();
    }
    if (tid < NBLK) g_boff[tid] = s[tid] - v;
}
__global__ __launch_bounds__(1024) void scan_add_kernel() {
    int i = blockIdx.x * 1024 + threadIdx.x;
    if (i < NN) g_rowptr[i + 1] += g_boff[blockIdx.x];
}

// ---------------------------------------------------------------- counting-sort scatter
__global__ void scatter_kernel(const void* __restrict__ ei, int E) {
    int e = blockIdx.x * blockDim.x + threadIdx.x;
    if (e < E) {
        int srcv = load_idx(ei, (size_t)e);
        int d    = load_idx(ei, (size_t)E + e);
        if ((unsigned)d < NN && (unsigned)srcv < NN) {
            int pos = g_rowptr[d] + atomicAdd(&g_fill[d], 1);
            if ((unsigned)pos < EMAX) g_esrc[pos] = srcv;
        }
    }
}

// ---------------------------------------------------------------- aggregate
// warp per node; full 32-chunks use clean ILP-8 path, partial chunks use
// masked ILP-8 groups (predicated loads) instead of a serial tail loop.
__global__ __launch_bounds__(256) void aggregate_kernel() {
    int gtid = blockIdx.x * blockDim.x + threadIdx.x;
    int w = gtid >> 5, lane = gtid & 31;
    if (w >= NN) return;
    int beg = g_rowptr[w], end = g_rowptr[w + 1];
    const __half2* __restrict__ base = (const __half2*)g_hhi;

    float2 ac[8];
#pragma unroll
    for (int i = 0; i < 8; i++) ac[i] = make_float2(0.f, 0.f);

    for (int j = beg; j < end; j += 32) {
        int jl = j + lane;
        int sidx = g_esrc[(jl < end) ? jl : beg];
        int m = end - j; if (m > 32) m = 32;
        if (m == 32) {
#pragma unroll
            for (int t = 0; t < 32; t += 8) {
                int sv[8];
#pragma unroll
                for (int u = 0; u < 8; u++) sv[u] = __shfl_sync(0xffffffffu, sidx, t + u);
                float2 v[8];
#pragma unroll
                for (int u = 0; u < 8; u++) v[u] = __half22float2(base[(size_t)sv[u] * 32 + lane]);
#pragma unroll
                for (int u = 0; u < 8; u++) { ac[u].x += v[u].x; ac[u].y += v[u].y; }
            }
        } else {
            for (int t = 0; t < m; t += 8) {
                int sv[8];
#pragma unroll
                for (int u = 0; u < 8; u++) {
                    int tt = t + u; tt = (tt < m) ? tt : 0;
                    sv[u] = __shfl_sync(0xffffffffu, sidx, tt);
                }
                float2 v[8];
#pragma unroll
                for (int u = 0; u < 8; u++) {
                    v[u] = make_float2(0.f, 0.f);
                    if (t + u < m) v[u] = __half22float2(base[(size_t)sv[u] * 32 + lane]);
                }
#pragma unroll
                for (int u = 0; u < 8; u++) { ac[u].x += v[u].x; ac[u].y += v[u].y; }
            }
        }
    }
    float inv = g_inv[w];
    float2 acc = make_float2(0.f, 0.f);
#pragma unroll
    for (int i = 0; i < 8; i++) { acc.x += ac[i].x; acc.y += ac[i].y; }
    acc.x *= inv; acc.y *= inv;
    *(__half2*)(g_agghi + (size_t)w * HD + lane * 2) = __floats2half2_rn(acc.x, acc.y);
}

// ================================================================ fp16-split MMA GEMMs
#define A2W 36
#define B2W 72

// split fp32 A tile into hi/lo smem planes (used by gemm_in only)
__device__ __forceinline__ void storeA_planes(__half2* Ah, __half2* Al,
                                              const float4* va, int tid) {
#pragma unroll
    for (int it = 0; it < 4; it++) {
        int idx = tid + it * 256;
        int r = idx >> 4, c4 = idx & 15;
        __half2 h0, l0, h1, l1;
        split2(va[it].x, va[it].y, h0, l0);
        split2(va[it].z, va[it].w, h1, l1);
        *(uint2*)(Ah + r * A2W + c4 * 2) = make_uint2(*(uint32_t*)&h0, *(uint32_t*)&h1);
        *(uint2*)(Al + r * A2W + c4 * 2) = make_uint2(*(uint32_t*)&l0, *(uint32_t*)&l1);
    }
}
// copy pre-split hi/lo planes from global into smem (no ALU)
__device__ __forceinline__ void copyA_planes(__half2* Ah, __half2* Al,
                                             const __half* hi, const __half* lo,
                                             int row0, int tid) {
#pragma unroll
    for (int it = 0; it < 4; it++) {
        int idx = tid + it * 256;
        int r = idx >> 4, c4 = idx & 15;
        int grow = row0 + r;
        uint2 vh = make_uint2(0u, 0u), vl = make_uint2(0u, 0u);
        if (grow < NN) {
            vh = *(const uint2*)(hi + (size_t)grow * 64 + c4 * 4);
            vl = *(const uint2*)(lo + (size_t)grow * 64 + c4 * 4);
        }
        *(uint2*)(Ah + r * A2W + c4 * 2) = vh;
        *(uint2*)(Al + r * A2W + c4 * 2) = vl;
    }
}
// copy hi-only plane (agg path)
__device__ __forceinline__ void copyA_hi(__half2* Ah, const __half* hi,
                                         int row0, int tid) {
#pragma unroll
    for (int it = 0; it < 4; it++) {
        int idx = tid + it * 256;
        int r = idx >> 4, c4 = idx & 15;
        int grow = row0 + r;
        uint2 vh = make_uint2(0u, 0u);
        if (grow < NN) vh = *(const uint2*)(hi + (size_t)grow * 64 + c4 * 4);
        *(uint2*)(Ah + r * A2W + c4 * 2) = vh;
    }
}
__device__ __forceinline__ void storeB_planes(__half2* Bh, __half2* Bl,
                                              const float4* vb, int tid) {
    int k2 = tid >> 3, ng = (tid & 7) * 8;
    const float* r0 = (const float*)&vb[0];
    const float* r1 = (const float*)&vb[2];
    __half2 hh[8], ll[8];
#pragma unroll
    for (int jj = 0; jj < 8; jj++) split2(r0[jj], r1[jj], hh[jj], ll[jj]);
    uint4* ph = (uint4*)(Bh + k2 * B2W + ng);
    uint4* pl = (uint4*)(Bl + k2 * B2W + ng);
    ph[0] = make_uint4(*(uint32_t*)&hh[0], *(uint32_t*)&hh[1], *(uint32_t*)&hh[2], *(uint32_t*)&hh[3]);
    ph[1] = make_uint4(*(uint32_t*)&hh[4], *(uint32_t*)&hh[5], *(uint32_t*)&hh[6], *(uint32_t*)&hh[7]);
    pl[0] = make_uint4(*(uint32_t*)&ll[0], *(uint32_t*)&ll[1], *(uint32_t*)&ll[2], *(uint32_t*)&ll[3]);
    pl[1] = make_uint4(*(uint32_t*)&ll[4], *(uint32_t*)&ll[5], *(uint32_t*)&ll[6], *(uint32_t*)&ll[7]);
}

// 3-product kstep (full precision: ah*bh + al*bh + ah*bl)
__device__ __forceinline__ void mma_kstep16(const __half2* Ah, const __half2* Al,
                                            const __half2* Bh, const __half2* Bl,
                                            int m0, int n0, int k2b,
                                            int qrow, int qcol, float acc[4][4]) {
    uint32_t ah[4], al[4];
    int ra = (m0 + qrow) * A2W + k2b + qcol;
    ah[0] = *(const uint32_t*)&Ah[ra];
    ah[1] = *(const uint32_t*)&Ah[ra + 8 * A2W];
    ah[2] = *(const uint32_t*)&Ah[ra + 4];
    ah[3] = *(const uint32_t*)&Ah[ra + 8 * A2W + 4];
    al[0] = *(const uint32_t*)&Al[ra];
    al[1] = *(const uint32_t*)&Al[ra + 8 * A2W];
    al[2] = *(const uint32_t*)&Al[ra + 4];
    al[3] = *(const uint32_t*)&Al[ra + 8 * A2W + 4];
#pragma unroll
    for (int nt = 0; nt < 4; nt++) {
        int nn = n0 + nt * 8;
        int rb = (k2b + qcol) * B2W + nn + qrow;
        uint32_t bh[2], bl2[2];
        bh[0]  = *(const uint32_t*)&Bh[rb];
        bh[1]  = *(const uint32_t*)&Bh[rb + 4 * B2W];
        bl2[0] = *(const uint32_t*)&Bl[rb];
        bl2[1] = *(const uint32_t*)&Bl[rb + 4 * B2W];
        mma_f16(acc[nt], ah, bh);
        mma_f16(acc[nt], al, bh);
        mma_f16(acc[nt], ah, bl2);
    }
}
// 2-product kstep (A hi only: ah*bh + ah*bl) — for agg chunk
__device__ __forceinline__ void mma_kstep16_hi(const __half2* Ah,
                                               const __half2* Bh, const __half2* Bl,
                                               int m0, int n0, int k2b,
                                               int qrow, int qcol, float acc[4][4]) {
    uint32_t ah[4];
    int ra = (m0 + qrow) * A2W + k2b + qcol;
    ah[0] = *(const uint32_t*)&Ah[ra];
    ah[1] = *(const uint32_t*)&Ah[ra + 8 * A2W];
    ah[2] = *(const uint32_t*)&Ah[ra + 4];
    ah[3] = *(const uint32_t*)&Ah[ra + 8 * A2W + 4];
#pragma unroll
    for (int nt = 0; nt < 4; nt++) {
        int nn = n0 + nt * 8;
        int rb = (k2b + qcol) * B2W + nn + qrow;
        uint32_t bh[2], bl2[2];
        bh[0]  = *(const uint32_t*)&Bh[rb];
        bh[1]  = *(const uint32_t*)&Bh[rb + 4 * B2W];
        bl2[0] = *(const uint32_t*)&Bl[rb];
        bl2[1] = *(const uint32_t*)&Bl[rb + 4 * B2W];
        mma_f16(acc[nt], ah, bh);
        mma_f16(acc[nt], ah, bl2);
    }
}

// ---------------------------------------------------------------- input GEMM: h = x @ Win + b_in
__global__ __launch_bounds__(256) void gemm_in_mma(const float* __restrict__ x,
                                                   const float* __restrict__ Win,
                                                   const float* __restrict__ bin) {
    __shared__ __align__(16) __half2 Ah[64 * A2W], Al[64 * A2W];
    __shared__ __align__(16) __half2 Bh[32 * B2W], Bl[32 * B2W];
    int tid = threadIdx.x;
    int wid = tid >> 5, lane = tid & 31;
    int warpM = wid & 3, warpN = wid >> 2;
    int qrow = lane >> 2, qcol = lane & 3;
    int row0 = blockIdx.x * 64;
    float acc[4][4];
#pragma unroll
    for (int nt = 0; nt < 4; nt++)
#pragma unroll
        for (int i = 0; i < 4; i++) acc[nt][i] = 0.f;

    float4 va[4], vb[4];
    {
        int k2 = tid >> 3, ng = (tid & 7) * 8;
#pragma unroll
        for (int it = 0; it < 4; it++) {
            int idx = tid + it * 256;
            int r = idx >> 4, c4 = idx & 15;
            int grow = row0 + r;
            va[it] = (grow < NN) ? *(const float4*)(x + (size_t)grow * 512 + c4 * 4)
                                 : make_float4(0.f, 0.f, 0.f, 0.f);
        }
        vb[0] = *(const float4*)(Win + (size_t)(2 * k2) * 64 + ng);
        vb[1] = *(const float4*)(Win + (size_t)(2 * k2) * 64 + ng + 4);
        vb[2] = *(const float4*)(Win + (size_t)(2 * k2 + 1) * 64 + ng);
        vb[3] = *(const float4*)(Win + (size_t)(2 * k2 + 1) * 64 + ng + 4);
    }
#pragma unroll 1
    for (int c = 0; c < 8; c++) {
        storeA_planes(Ah, Al, va, tid);
        storeB_planes(Bh, Bl, vb, tid);
        __syncthreads();
        if (c < 7) {
            int kc = (c + 1) * 64;
            int k2 = tid >> 3, ng = (tid & 7) * 8;
#pragma unroll
            for (int it = 0; it < 4; it++) {
                int idx = tid + it * 256;
                int r = idx >> 4, c4 = idx & 15;
                int grow = row0 + r;
                va[it] = (grow < NN) ? *(const float4*)(x + (size_t)grow * 512 + kc + c4 * 4)
                                     : make_float4(0.f, 0.f, 0.f, 0.f);
            }
            vb[0] = *(const float4*)(Win + (size_t)(kc + 2 * k2) * 64 + ng);
            vb[1] = *(const float4*)(Win + (size_t)(kc + 2 * k2) * 64 + ng + 4);
            vb[2] = *(const float4*)(Win + (size_t)(kc + 2 * k2 + 1) * 64 + ng);
            vb[3] = *(const float4*)(Win + (size_t)(kc + 2 * k2 + 1) * 64 + ng + 4);
        }
#pragma unroll
        for (int kk = 0; kk < 4; kk++)
            mma_kstep16(Ah, Al, Bh, Bl, warpM * 16, warpN * 32, kk * 8, qrow, qcol, acc);
        __syncthreads();
    }
#pragma unroll
    for (int nt = 0; nt < 4; nt++) {
        int gc = warpN * 32 + nt * 8 + qcol * 2;
        float2 bv = *(const float2*)(bin + gc);
#pragma unroll
        for (int half = 0; half < 2; half++) {
            int gr = row0 + warpM * 16 + qrow + half * 8;
            if (gr < NN) {
                float ox = acc[nt][half * 2 + 0] + bv.x;
                float oy = acc[nt][half * 2 + 1] + bv.y;
                __half2 hi, lo;
                split2(ox, oy, hi, lo);
                *(__half2*)(g_hhi + (size_t)gr * 64 + gc) = hi;
                *(__half2*)(g_hlo + (size_t)gr * 64 + gc) = lo;
            }
        }
    }
}

// ---------------------------------------------------------------- layer GEMM:
// h = h + relu(agg @ Wl + bl + h @ Wr); chunk0 = agg(hi-only), chunk1 = h(hi/lo)
__global__ __launch_bounds__(256) void gemm_layer_mma(const float* __restrict__ Wl,
                                                      const float* __restrict__ Wr,
                                                      const float* __restrict__ bl) {
    __shared__ __align__(16) __half2 Ah[64 * A2W], Al[64 * A2W];
    __shared__ __align__(16) __half2 Bh[32 * B2W], Bl[32 * B2W];
    int tid = threadIdx.x;
    int wid = tid >> 5, lane = tid & 31;
    int warpM = wid & 3, warpN = wid >> 2;
    int qrow = lane >> 2, qcol = lane & 3;
    int row0 = blockIdx.x * 64;
    float acc[4][4];
#pragma unroll
    for (int nt = 0; nt < 4; nt++)
#pragma unroll
        for (int i = 0; i < 4; i++) acc[nt][i] = 0.f;

    // ---- chunk 0: agg (hi only) @ Wl
    {
        float4 vb[4];
        int k2 = tid >> 3, ng = (tid & 7) * 8;
        vb[0] = *(const float4*)(Wl + (size_t)(2 * k2) * 64 + ng);
        vb[1] = *(const float4*)(Wl + (size_t)(2 * k2) * 64 + ng + 4);
        vb[2] = *(const float4*)(Wl + (size_t)(2 * k2 + 1) * 64 + ng);
        vb[3] = *(const float4*)(Wl + (size_t)(2 * k2 + 1) * 64 + ng + 4);
        copyA_hi(Ah, g_agghi, row0, tid);
        storeB_planes(Bh, Bl, vb, tid);
        __syncthreads();
#pragma unroll
        for (int kk = 0; kk < 4; kk++)
            mma_kstep16_hi(Ah, Bh, Bl, warpM * 16, warpN * 32, kk * 8, qrow, qcol, acc);
        __syncthreads();
    }
    // ---- chunk 1: h (hi/lo) @ Wr
    {
        float4 vb[4];
        int k2 = tid >> 3, ng = (tid & 7) * 8;
        vb[0] = *(const float4*)(Wr + (size_t)(2 * k2) * 64 + ng);
        vb[1] = *(const float4*)(Wr + (size_t)(2 * k2) * 64 + ng + 4);
        vb[2] = *(const float4*)(Wr + (size_t)(2 * k2 + 1) * 64 + ng);
        vb[3] = *(const float4*)(Wr + (size_t)(2 * k2 + 1) * 64 + ng + 4);
        copyA_planes(Ah, Al, g_hhi, g_hlo, row0, tid);
        storeB_planes(Bh, Bl, vb, tid);
        __syncthreads();
#pragma unroll
        for (int kk = 0; kk < 4; kk++)
            mma_kstep16(Ah, Al, Bh, Bl, warpM * 16, warpN * 32, kk * 8, qrow, qcol, acc);
    }
    // ---- epilogue: h += relu(acc + bl); h reconstructed hi+lo, stored back hi/lo
#pragma unroll
    for (int nt = 0; nt < 4; nt++) {
        int gc = warpN * 32 + nt * 8 + qcol * 2;
        float2 bv = *(const float2*)(bl + gc);
#pragma unroll
        for (int half = 0; half < 2; half++) {
            int gr = row0 + warpM * 16 + qrow + half * 8;
            if (gr < NN) {
                float2 oh = __half22float2(*(const __half2*)(g_hhi + (size_t)gr * 64 + gc));
                float2 ol = __half22float2(*(const __half2*)(g_hlo + (size_t)gr * 64 + gc));
                float ox = (oh.x + ol.x) + fmaxf(acc[nt][half * 2 + 0] + bv.x, 0.f);
                float oy = (oh.y + ol.y) + fmaxf(acc[nt][half * 2 + 1] + bv.y, 0.f);
                __half2 hi, lo;
                split2(ox, oy, hi, lo);
                *(__half2*)(g_hhi + (size_t)gr * 64 + gc) = hi;
                *(__half2*)(g_hlo + (size_t)gr * 64 + gc) = lo;
            }
        }
    }
}

// ---------------------------------------------------------------- output GEMM: out = h @ Wout + b_out
__global__ __launch_bounds__(256) void gemm_out_mma(const float* __restrict__ Wout,
                                                    const float* __restrict__ bout,
                                                    float* __restrict__ out) {
    __shared__ __align__(16) __half2 Ah[64 * A2W], Al[64 * A2W];
    __shared__ __align__(16) __half2 Bh[32 * B2W], Bl[32 * B2W];
    int tid = threadIdx.x;
    int wid = tid >> 5, lane = tid & 31;
    int warpM = wid & 3, warpN = wid >> 2;
    int qrow = lane >> 2, qcol = lane & 3;
    int row0 = blockIdx.x * 64;
    int col0 = blockIdx.y * 64;
    float acc[4][4];
#pragma unroll
    for (int nt = 0; nt < 4; nt++)
#pragma unroll
        for (int i = 0; i < 4; i++) acc[nt][i] = 0.f;

    {
        float4 vb[4];
        int k2 = tid >> 3, ng = (tid & 7) * 8;
        vb[0] = *(const float4*)(Wout + (size_t)(2 * k2) * 256 + col0 + ng);
        vb[1] = *(const float4*)(Wout + (size_t)(2 * k2) * 256 + col0 + ng + 4);
        vb[2] = *(const float4*)(Wout + (size_t)(2 * k2 + 1) * 256 + col0 + ng);
        vb[3] = *(const float4*)(Wout + (size_t)(2 * k2 + 1) * 256 + col0 + ng + 4);
        copyA_planes(Ah, Al, g_hhi, g_hlo, row0, tid);
        storeB_planes(Bh, Bl, vb, tid);
    }
    __syncthreads();
#pragma unroll
    for (int kk = 0; kk < 4; kk++)
        mma_kstep16(Ah, Al, Bh, Bl, warpM * 16, warpN * 32, kk * 8, qrow, qcol, acc);

#pragma unroll
    for (int nt = 0; nt < 4; nt++) {
        int gc = warpN * 32 + nt * 8 + qcol * 2;
        float2 bv = *(const float2*)(bout + col0 + gc);
#pragma unroll
        for (int half = 0; half < 2; half++) {
            int gr = row0 + warpM * 16 + qrow + half * 8;
            if (gr < NN) {
                float2 o;
                o.x = acc[nt][half * 2 + 0] + bv.x;
                o.y = acc[nt][half * 2 + 1] + bv.y;
                *(float2*)(out + (size_t)gr * 256 + col0 + gc) = o;
            }
        }
    }
}

// ---------------------------------------------------------------- launch
extern "C" void kernel_launch(void* const* d_in, const int* in_sizes, int n_in,
                              void* d_out, int out_size) {
    const float* x    = (const float*)d_in[0];
    const void*  ei   = d_in[1];
    const float* Win  = (const float*)d_in[2];
    const float* bin  = (const float*)d_in[3];
    const float* Wl   = (const float*)d_in[4];
    const float* bl   = (const float*)d_in[5];
    const float* Wr   = (const float*)d_in[6];
    const float* Wout = (const float*)d_in[7];
    const float* bout = (const float*)d_in[8];
    float* out = (float*)d_out;
    int E = in_sizes[1] / 2;

    static cudaStream_t s_side = nullptr;
    static cudaEvent_t  e_fork = nullptr, e_join = nullptr;
    if (s_side == nullptr) {
        cudaStreamCreateWithFlags(&s_side, cudaStreamNonBlocking);
        cudaEventCreateWithFlags(&e_fork, cudaEventDisableTiming);
        cudaEventCreateWithFlags(&e_join, cudaEventDisableTiming);
    }

    cudaEventRecord(e_fork, 0);
    cudaStreamWaitEvent(s_side, e_fork, 0);

    // ---- side stream: CSR build chain (edge_index only)
    detect_kernel<<<1, 32, 0, s_side>>>((const int*)ei);
    zero_kernel<<<(NN + 255) / 256, 256, 0, s_side>>>();
    degree_kernel<<<(E + 255) / 256, 256, 0, s_side>>>(ei, E);
    scan_partial_kernel<<<NBLK, 1024, 0, s_side>>>();
    scan_bsum_kernel<<<1, 128, 0, s_side>>>();
    scan_add_kernel<<<NBLK, 1024, 0, s_side>>>();
    scatter_kernel<<<(E + 255) / 256, 256, 0, s_side>>>(ei, E);
    cudaEventRecord(e_join, s_side);

    // ---- main stream: input GEMM — overlaps CSR build
    gemm_in_mma<<<MBLK, 256>>>(x, Win, bin);

    cudaStreamWaitEvent(0, e_join, 0);

    for (int i = 0; i < 4; i++) {
        aggregate_kernel<<<(NN * 32 + 255) / 256, 256>>>();
        gemm_layer_mma<<<MBLK, 256>>>(Wl + i * HD * HD, Wr + i * HD * HD, bl + i * HD);
    }

    gemm_out_mma<<<dim3(MBLK, 4), 256>>>(Wout, bout, out);
}

// round 13
// speedup vs baseline: 1.0833x; 1.0833x over previous
#include <cuda_runtime.h>
#include <cuda_fp16.h>
#include <cstdint>

#define NN   100000
#define HD   64
#define EMAX 3200000
#define NBLK ((NN + 1023) / 1024)   // 98
#define MBLK ((NN + 63) / 64)       // 1563

// ---- scratch (device globals; no allocation allowed) ----
__device__ __align__(16) float  g_h[NN * HD];     // node features fp32 (25.6 MB)
__device__ __align__(16) __half g_h16[NN * HD];   // fp16 mirror for gather (12.8 MB)
__device__ __align__(16) float  g_agg[NN * HD];   // aggregated neighbor features
__device__ int   g_cnt[NN];
__device__ float g_inv[NN];
__device__ int   g_rowptr[NN + 1];
__device__ int   g_fill[NN];
__device__ int   g_esrc[EMAX];
__device__ int   g_is64;
__device__ int   g_bsum[NBLK];
__device__ int   g_boff[NBLK];

// ---------------------------------------------------------------- fp16 split mma helpers
__device__ __forceinline__ void mma_f16(float* d, const uint32_t* a, const uint32_t* b) {
    asm volatile(
        "mma.sync.aligned.m16n8k16.row.col.f32.f16.f16.f32 "
        "{%0,%1,%2,%3}, {%4,%5,%6,%7}, {%8,%9}, {%0,%1,%2,%3};\n"
        : "+f"(d[0]), "+f"(d[1]), "+f"(d[2]), "+f"(d[3])
        : "r"(a[0]), "r"(a[1]), "r"(a[2]), "r"(a[3]), "r"(b[0]), "r"(b[1]));
}
__device__ __forceinline__ void split2(float a, float b, __half2& hi, __half2& lo) {
    __half ha = __float2half_rn(a), hb = __float2half_rn(b);
    hi = __halves2half2(ha, hb);
    lo = __floats2half2_rn(a - __half2float(ha), b - __half2float(hb));
}

// ---------------------------------------------------------------- dtype probe
__global__ void detect_kernel(const int* __restrict__ ei32) {
    if (threadIdx.x == 0 && blockIdx.x == 0) {
        int nz = 0;
        for (int k = 0; k < 64; k++) nz |= ei32[2 * k + 1];
        g_is64 = (nz == 0) ? 1 : 0;
    }
}
__device__ __forceinline__ int load_idx(const void* ei, size_t pos) {
    if (g_is64) return (int)((const long long*)ei)[pos];
    return ((const int*)ei)[pos];
}

// ---------------------------------------------------------------- zero / degree
__global__ void zero_kernel() {
    int i = blockIdx.x * blockDim.x + threadIdx.x;
    if (i < NN) { g_cnt[i] = 0; g_fill[i] = 0; }
}
__global__ void degree_kernel(const void* __restrict__ ei, int E) {
    int e = blockIdx.x * blockDim.x + threadIdx.x;
    if (e < E) {
        int d = load_idx(ei, (size_t)E + e);
        if ((unsigned)d < NN) atomicAdd(&g_cnt[d], 1);
    }
}

// ---------------------------------------------------------------- hierarchical scan
__global__ __launch_bounds__(1024) void scan_partial_kernel() {
    __shared__ int s[1024];
    int tid = threadIdx.x, b = blockIdx.x;
    int i = b * 1024 + tid;
    int v = (i < NN) ? g_cnt[i] : 0;
    if (i < NN) g_inv[i] = 1.0f / fmaxf((float)v, 1.0f);
    s[tid] = v;
    __syncthreads();
#pragma unroll
    for (int off = 1; off < 1024; off <<= 1) {
        int t = (tid >= off) ? s[tid - off] : 0;
        __syncthreads();
        s[tid] += t;
        __syncthreads();
    }
    if (i < NN) g_rowptr[i + 1] = s[tid];
    if (tid == 1023) g_bsum[b] = s[1023];
    if (i == 0) g_rowptr[0] = 0;
}
__global__ void scan_bsum_kernel() {
    __shared__ int s[128];
    int tid = threadIdx.x;
    int v = (tid < NBLK) ? g_bsum[tid] : 0;
    s[tid] = v;
    __syncthreads();
#pragma unroll
    for (int off = 1; off < 128; off <<= 1) {
        int t = (tid >= off) ? s[tid - off] : 0;
        __syncthreads();
        s[tid] += t;
        __syncthreads();
    }
    if (tid < NBLK) g_boff[tid] = s[tid] - v;
}
__global__ __launch_bounds__(1024) void scan_add_kernel() {
    int i = blockIdx.x * 1024 + threadIdx.x;
    if (i < NN) g_rowptr[i + 1] += g_boff[blockIdx.x];
}

// ---------------------------------------------------------------- counting-sort scatter
__global__ void scatter_kernel(const void* __restrict__ ei, int E) {
    int e = blockIdx.x * blockDim.x + threadIdx.x;
    if (e < E) {
        int srcv = load_idx(ei, (size_t)e);
        int d    = load_idx(ei, (size_t)E + e);
        if ((unsigned)d < NN && (unsigned)srcv < NN) {
            int pos = g_rowptr[d] + atomicAdd(&g_fill[d], 1);
            if ((unsigned)pos < EMAX) g_esrc[pos] = srcv;
        }
    }
}

// ---------------------------------------------------------------- aggregate
// HALF-WARP per node: 16 lanes each load uint2 (4 halves) of the row — one
// warp-wide load instruction covers 2 nodes. ILP-4 per half-warp.
// Same loop structure as R10 (pre-split full chunks + serial tail).
__global__ __launch_bounds__(256) void aggregate_kernel() {
    int gid = blockIdx.x * 256 + threadIdx.x;
    int node = gid >> 4;
    if (node >= NN) return;
    int sub = threadIdx.x & 15;
    int beg = g_rowptr[node], end = g_rowptr[node + 1];
    const uint2* __restrict__ base = (const uint2*)g_h16;   // 16 uint2 per 64-half row

    float2 a0[4], a1[4];
#pragma unroll
    for (int i = 0; i < 4; i++) { a0[i] = make_float2(0.f, 0.f); a1[i] = make_float2(0.f, 0.f); }

    int n = end - beg;
    int nfull = n & ~15;
    int j = beg;
    for (; j < beg + nfull; j += 16) {
        int sidx = g_esrc[j + sub];
#pragma unroll
        for (int t = 0; t < 16; t += 4) {
            int sv[4];
#pragma unroll
            for (int u = 0; u < 4; u++) sv[u] = __shfl_sync(0xffffffffu, sidx, t + u, 16);
            uint2 d[4];
#pragma unroll
            for (int u = 0; u < 4; u++) d[u] = base[(size_t)sv[u] * 16 + sub];
#pragma unroll
            for (int u = 0; u < 4; u++) {
                float2 v0 = __half22float2(*(__half2*)&d[u].x);
                float2 v1 = __half22float2(*(__half2*)&d[u].y);
                a0[u].x += v0.x; a0[u].y += v0.y;
                a1[u].x += v1.x; a1[u].y += v1.y;
            }
        }
    }
    if (j < end) {
        int jl = j + sub;
        int sidx = (jl < end) ? g_esrc[jl] : 0;
        int m = end - j;
        for (int t = 0; t < m; t++) {
            int sv = __shfl_sync(0xffffffffu, sidx, t, 16);
            uint2 d = base[(size_t)sv * 16 + sub];
            float2 v0 = __half22float2(*(__half2*)&d.x);
            float2 v1 = __half22float2(*(__half2*)&d.y);
            a0[0].x += v0.x; a0[0].y += v0.y;
            a1[0].x += v1.x; a1[0].y += v1.y;
        }
    }
    float inv = g_inv[node];
    float2 s0 = make_float2(0.f, 0.f), s1 = make_float2(0.f, 0.f);
#pragma unroll
    for (int i = 0; i < 4; i++) {
        s0.x += a0[i].x; s0.y += a0[i].y;
        s1.x += a1[i].x; s1.y += a1[i].y;
    }
    float4 o;
    o.x = s0.x * inv; o.y = s0.y * inv;
    o.z = s1.x * inv; o.w = s1.y * inv;
    *(float4*)(g_agg + (size_t)node * HD + sub * 4) = o;
}

// ================================================================ fp16-split MMA GEMMs
#define A2W 36
#define B2W 72

__device__ __forceinline__ void storeA_planes(__half2* Ah, __half2* Al,
                                              const float4* va, int tid) {
#pragma unroll
    for (int it = 0; it < 4; it++) {
        int idx = tid + it * 256;
        int r = idx >> 4, c4 = idx & 15;
        __half2 h0, l0, h1, l1;
        split2(va[it].x, va[it].y, h0, l0);
        split2(va[it].z, va[it].w, h1, l1);
        __half2* ph = Ah + r * A2W + c4 * 2;
        __half2* pl = Al + r * A2W + c4 * 2;
        *(uint2*)ph = make_uint2(*(uint32_t*)&h0, *(uint32_t*)&h1);
        *(uint2*)pl = make_uint2(*(uint32_t*)&l0, *(uint32_t*)&l1);
    }
}
__device__ __forceinline__ void storeB_planes(__half2* Bh, __half2* Bl,
                                              const float4* vb, int tid) {
    int k2 = tid >> 3, ng = (tid & 7) * 8;
    const float* r0 = (const float*)&vb[0];
    const float* r1 = (const float*)&vb[2];
    __half2 hh[8], ll[8];
#pragma unroll
    for (int jj = 0; jj < 8; jj++) split2(r0[jj], r1[jj], hh[jj], ll[jj]);
    uint4* ph = (uint4*)(Bh + k2 * B2W + ng);
    uint4* pl = (uint4*)(Bl + k2 * B2W + ng);
    ph[0] = make_uint4(*(uint32_t*)&hh[0], *(uint32_t*)&hh[1], *(uint32_t*)&hh[2], *(uint32_t*)&hh[3]);
    ph[1] = make_uint4(*(uint32_t*)&hh[4], *(uint32_t*)&hh[5], *(uint32_t*)&hh[6], *(uint32_t*)&hh[7]);
    pl[0] = make_uint4(*(uint32_t*)&ll[0], *(uint32_t*)&ll[1], *(uint32_t*)&ll[2], *(uint32_t*)&ll[3]);
    pl[1] = make_uint4(*(uint32_t*)&ll[4], *(uint32_t*)&ll[5], *(uint32_t*)&ll[6], *(uint32_t*)&ll[7]);
}

__device__ __forceinline__ void mma_kstep16(const __half2* Ah, const __half2* Al,
                                            const __half2* Bh, const __half2* Bl,
                                            int m0, int n0, int k2b,
                                            int qrow, int qcol, float acc[4][4]) {
    uint32_t ah[4], al[4];
    int ra = (m0 + qrow) * A2W + k2b + qcol;
    ah[0] = *(const uint32_t*)&Ah[ra];
    ah[1] = *(const uint32_t*)&Ah[ra + 8 * A2W];
    ah[2] = *(const uint32_t*)&Ah[ra + 4];
    ah[3] = *(const uint32_t*)&Ah[ra + 8 * A2W + 4];
    al[0] = *(const uint32_t*)&Al[ra];
    al[1] = *(const uint32_t*)&Al[ra + 8 * A2W];
    al[2] = *(const uint32_t*)&Al[ra + 4];
    al[3] = *(const uint32_t*)&Al[ra + 8 * A2W + 4];
#pragma unroll
    for (int nt = 0; nt < 4; nt++) {
        int nn = n0 + nt * 8;
        int rb = (k2b + qcol) * B2W + nn + qrow;
        uint32_t bh[2], bl2[2];
        bh[0]  = *(const uint32_t*)&Bh[rb];
        bh[1]  = *(const uint32_t*)&Bh[rb + 4 * B2W];
        bl2[0] = *(const uint32_t*)&Bl[rb];
        bl2[1] = *(const uint32_t*)&Bl[rb + 4 * B2W];
        mma_f16(acc[nt], ah, bh);
        mma_f16(acc[nt], al, bh);
        mma_f16(acc[nt], ah, bl2);
    }
}

// ---------------------------------------------------------------- input GEMM: h = x @ Win + b_in
__global__ __launch_bounds__(256) void gemm_in_mma(const float* __restrict__ x,
                                                   const float* __restrict__ Win,
                                                   const float* __restrict__ bin) {
    __shared__ __align__(16) __half2 Ah[64 * A2W], Al[64 * A2W];
    __shared__ __align__(16) __half2 Bh[32 * B2W], Bl[32 * B2W];
    int tid = threadIdx.x;
    int wid = tid >> 5, lane = tid & 31;
    int warpM = wid & 3, warpN = wid >> 2;
    int qrow = lane >> 2, qcol = lane & 3;
    int row0 = blockIdx.x * 64;
    float acc[4][4];
#pragma unroll
    for (int nt = 0; nt < 4; nt++)
#pragma unroll
        for (int i = 0; i < 4; i++) acc[nt][i] = 0.f;

    float4 va[4], vb[4];
    {
        int k2 = tid >> 3, ng = (tid & 7) * 8;
#pragma unroll
        for (int it = 0; it < 4; it++) {
            int idx = tid + it * 256;
            int r = idx >> 4, c4 = idx & 15;
            int grow = row0 + r;
            va[it] = (grow < NN) ? *(const float4*)(x + (size_t)grow * 512 + c4 * 4)
                                 : make_float4(0.f, 0.f, 0.f, 0.f);
        }
        vb[0] = *(const float4*)(Win + (size_t)(2 * k2) * 64 + ng);
        vb[1] = *(const float4*)(Win + (size_t)(2 * k2) * 64 + ng + 4);
        vb[2] = *(const float4*)(Win + (size_t)(2 * k2 + 1) * 64 + ng);
        vb[3] = *(const float4*)(Win + (size_t)(2 * k2 + 1) * 64 + ng + 4);
    }
#pragma unroll 1
    for (int c = 0; c < 8; c++) {
        storeA_planes(Ah, Al, va, tid);
        storeB_planes(Bh, Bl, vb, tid);
        __syncthreads();
        if (c < 7) {
            int kc = (c + 1) * 64;
            int k2 = tid >> 3, ng = (tid & 7) * 8;
#pragma unroll
            for (int it = 0; it < 4; it++) {
                int idx = tid + it * 256;
                int r = idx >> 4, c4 = idx & 15;
                int grow = row0 + r;
                va[it] = (grow < NN) ? *(const float4*)(x + (size_t)grow * 512 + kc + c4 * 4)
                                     : make_float4(0.f, 0.f, 0.f, 0.f);
            }
            vb[0] = *(const float4*)(Win + (size_t)(kc + 2 * k2) * 64 + ng);
            vb[1] = *(const float4*)(Win + (size_t)(kc + 2 * k2) * 64 + ng + 4);
            vb[2] = *(const float4*)(Win + (size_t)(kc + 2 * k2 + 1) * 64 + ng);
            vb[3] = *(const float4*)(Win + (size_t)(kc + 2 * k2 + 1) * 64 + ng + 4);
        }
#pragma unroll
        for (int kk = 0; kk < 4; kk++)
            mma_kstep16(Ah, Al, Bh, Bl, warpM * 16, warpN * 32, kk * 8, qrow, qcol, acc);
        __syncthreads();
    }
#pragma unroll
    for (int nt = 0; nt < 4; nt++) {
        int gc = warpN * 32 + nt * 8 + qcol * 2;
        float2 bv = *(const float2*)(bin + gc);
#pragma unroll
        for (int half = 0; half < 2; half++) {
            int gr = row0 + warpM * 16 + qrow + half * 8;
            if (gr < NN) {
                float2 o;
                o.x = acc[nt][half * 2 + 0] + bv.x;
                o.y = acc[nt][half * 2 + 1] + bv.y;
                *(float2*)(g_h + (size_t)gr * 64 + gc) = o;
                *(__half2*)(g_h16 + (size_t)gr * 64 + gc) = __floats2half2_rn(o.x, o.y);
            }
        }
    }
}

// ---------------------------------------------------------------- layer GEMM
__global__ __launch_bounds__(256) void gemm_layer_mma(const float* __restrict__ Wl,
                                                      const float* __restrict__ Wr,
                                                      const float* __restrict__ bl) {
    __shared__ __align__(16) __half2 Ah[64 * A2W], Al[64 * A2W];
    __shared__ __align__(16) __half2 Bh[32 * B2W], Bl[32 * B2W];
    int tid = threadIdx.x;
    int wid = tid >> 5, lane = tid & 31;
    int warpM = wid & 3, warpN = wid >> 2;
    int qrow = lane >> 2, qcol = lane & 3;
    int row0 = blockIdx.x * 64;
    float acc[4][4];
#pragma unroll
    for (int nt = 0; nt < 4; nt++)
#pragma unroll
        for (int i = 0; i < 4; i++) acc[nt][i] = 0.f;

#pragma unroll
    for (int c = 0; c < 2; c++) {
        const float* Asrc = c ? g_h : g_agg;
        const float* Bsrc = c ? Wr : Wl;
        float4 va[4], vb[4];
        int k2 = tid >> 3, ng = (tid & 7) * 8;
#pragma unroll
        for (int it = 0; it < 4; it++) {
            int idx = tid + it * 256;
            int r = idx >> 4, c4 = idx & 15;
            int grow = row0 + r;
            va[it] = (grow < NN) ? *(const float4*)(Asrc + (size_t)grow * 64 + c4 * 4)
                                 : make_float4(0.f, 0.f, 0.f, 0.f);
        }
        vb[0] = *(const float4*)(Bsrc + (size_t)(2 * k2) * 64 + ng);
        vb[1] = *(const float4*)(Bsrc + (size_t)(2 * k2) * 64 + ng + 4);
        vb[2] = *(const float4*)(Bsrc + (size_t)(2 * k2 + 1) * 64 + ng);
        vb[3] = *(const float4*)(Bsrc + (size_t)(2 * k2 + 1) * 64 + ng + 4);
        storeA_planes(Ah, Al, va, tid);
        storeB_planes(Bh, Bl, vb, tid);
        __syncthreads();
#pragma unroll
        for (int kk = 0; kk < 4; kk++)
            mma_kstep16(Ah, Al, Bh, Bl, warpM * 16, warpN * 32, kk * 8, qrow, qcol, acc);
        __syncthreads();
    }
#pragma unroll
    for (int nt = 0; nt < 4; nt++) {
        int gc = warpN * 32 + nt * 8 + qcol * 2;
        float2 bv = *(const float2*)(bl + gc);
#pragma unroll
        for (int half = 0; half < 2; half++) {
            int gr = row0 + warpM * 16 + qrow + half * 8;
            if (gr < NN) {
                float2 old = *(const float2*)(g_h + (size_t)gr * 64 + gc);
                float2 o;
                o.x = old.x + fmaxf(acc[nt][half * 2 + 0] + bv.x, 0.f);
                o.y = old.y + fmaxf(acc[nt][half * 2 + 1] + bv.y, 0.f);
                *(float2*)(g_h + (size_t)gr * 64 + gc) = o;
                *(__half2*)(g_h16 + (size_t)gr * 64 + gc) = __floats2half2_rn(o.x, o.y);
            }
        }
    }
}

// ---------------------------------------------------------------- output GEMM
__global__ __launch_bounds__(256) void gemm_out_mma(const float* __restrict__ Wout,
                                                    const float* __restrict__ bout,
                                                    float* __restrict__ out) {
    __shared__ __align__(16) __half2 Ah[64 * A2W], Al[64 * A2W];
    __shared__ __align__(16) __half2 Bh[32 * B2W], Bl[32 * B2W];
    int tid = threadIdx.x;
    int wid = tid >> 5, lane = tid & 31;
    int warpM = wid & 3, warpN = wid >> 2;
    int qrow = lane >> 2, qcol = lane & 3;
    int row0 = blockIdx.x * 64;
    int col0 = blockIdx.y * 64;
    float acc[4][4];
#pragma unroll
    for (int nt = 0; nt < 4; nt++)
#pragma unroll
        for (int i = 0; i < 4; i++) acc[nt][i] = 0.f;

    {
        float4 va[4], vb[4];
        int k2 = tid >> 3, ng = (tid & 7) * 8;
#pragma unroll
        for (int it = 0; it < 4; it++) {
            int idx = tid + it * 256;
            int r = idx >> 4, c4 = idx & 15;
            int grow = row0 + r;
            va[it] = (grow < NN) ? *(const float4*)(g_h + (size_t)grow * 64 + c4 * 4)
                                 : make_float4(0.f, 0.f, 0.f, 0.f);
        }
        vb[0] = *(const float4*)(Wout + (size_t)(2 * k2) * 256 + col0 + ng);
        vb[1] = *(const float4*)(Wout + (size_t)(2 * k2) * 256 + col0 + ng + 4);
        vb[2] = *(const float4*)(Wout + (size_t)(2 * k2 + 1) * 256 + col0 + ng);
        vb[3] = *(const float4*)(Wout + (size_t)(2 * k2 + 1) * 256 + col0 + ng + 4);
        storeA_planes(Ah, Al, va, tid);
        storeB_planes(Bh, Bl, vb, tid);
    }
    __syncthreads();
#pragma unroll
    for (int kk = 0; kk < 4; kk++)
        mma_kstep16(Ah, Al, Bh, Bl, warpM * 16, warpN * 32, kk * 8, qrow, qcol, acc);

#pragma unroll
    for (int nt = 0; nt < 4; nt++) {
        int gc = warpN * 32 + nt * 8 + qcol * 2;
        float2 bv = *(const float2*)(bout + col0 + gc);
#pragma unroll
        for (int half = 0; half < 2; half++) {
            int gr = row0 + warpM * 16 + qrow + half * 8;
            if (gr < NN) {
                float2 o;
                o.x = acc[nt][half * 2 + 0] + bv.x;
                o.y = acc[nt][half * 2 + 1] + bv.y;
                *(float2*)(out + (size_t)gr * 256 + col0 + gc) = o;
            }
        }
    }
}

// ---------------------------------------------------------------- launch
extern "C" void kernel_launch(void* const* d_in, const int* in_sizes, int n_in,
                              void* d_out, int out_size) {
    const float* x    = (const float*)d_in[0];
    const void*  ei   = d_in[1];
    const float* Win  = (const float*)d_in[2];
    const float* bin  = (const float*)d_in[3];
    const float* Wl   = (const float*)d_in[4];
    const float* bl   = (const float*)d_in[5];
    const float* Wr   = (const float*)d_in[6];
    const float* Wout = (const float*)d_in[7];
    const float* bout = (const float*)d_in[8];
    float* out = (float*)d_out;
    int E = in_sizes[1] / 2;

    static cudaStream_t s_side = nullptr;
    static cudaEvent_t  e_fork = nullptr, e_join = nullptr;
    if (s_side == nullptr) {
        cudaStreamCreateWithFlags(&s_side, cudaStreamNonBlocking);
        cudaEventCreateWithFlags(&e_fork, cudaEventDisableTiming);
        cudaEventCreateWithFlags(&e_join, cudaEventDisableTiming);
    }

    cudaEventRecord(e_fork, 0);
    cudaStreamWaitEvent(s_side, e_fork, 0);

    // ---- side stream: CSR build chain (edge_index only)
    detect_kernel<<<1, 32, 0, s_side>>>((const int*)ei);
    zero_kernel<<<(NN + 255) / 256, 256, 0, s_side>>>();
    degree_kernel<<<(E + 255) / 256, 256, 0, s_side>>>(ei, E);
    scan_partial_kernel<<<NBLK, 1024, 0, s_side>>>();
    scan_bsum_kernel<<<1, 128, 0, s_side>>>();
    scan_add_kernel<<<NBLK, 1024, 0, s_side>>>();
    scatter_kernel<<<(E + 255) / 256, 256, 0, s_side>>>(ei, E);
    cudaEventRecord(e_join, s_side);

    // ---- main stream: input GEMM — overlaps CSR build
    gemm_in_mma<<<MBLK, 256>>>(x, Win, bin);

    cudaStreamWaitEvent(0, e_join, 0);

    for (int i = 0; i < 4; i++) {
        aggregate_kernel<<<(NN * 16 + 255) / 256, 256>>>();
        gemm_layer_mma<<<MBLK, 256>>>(Wl + i * HD * HD, Wr + i * HD * HD, bl + i * HD);
    }

    gemm_out_mma<<<dim3(MBLK, 4), 256>>>(Wout, bout, out);
}

// round 14
// speedup vs baseline: 1.2308x; 1.1362x over previous
#include <cuda_runtime.h>
#include <cuda_fp16.h>
#include <cstdint>

#define NN   100000
#define HD   64
#define EMAX 3200000
#define NBLK ((NN + 1023) / 1024)   // 98
#define MBLK ((NN + 63) / 64)       // 1563

// ---- scratch (device globals; no allocation allowed) ----
__device__ __align__(16) float  g_h[NN * HD];      // node features fp32 (25.6 MB)
__device__ __align__(16) __half g_h16[NN * HD];    // fp16 mirror for gather (12.8 MB)
__device__ __align__(16) __half g_agg16[NN * HD];  // aggregated neighbors, fp16 (12.8 MB)
__device__ int   g_cnt[NN];
__device__ float g_inv[NN];
__device__ int   g_rowptr[NN + 1];
__device__ int   g_fill[NN];
__device__ int   g_esrc[EMAX];
__device__ int   g_is64;
__device__ int   g_bsum[NBLK];
__device__ int   g_boff[NBLK];

// ---------------------------------------------------------------- fp16 split mma helpers
__device__ __forceinline__ void mma_f16(float* d, const uint32_t* a, const uint32_t* b) {
    asm volatile(
        "mma.sync.aligned.m16n8k16.row.col.f32.f16.f16.f32 "
        "{%0,%1,%2,%3}, {%4,%5,%6,%7}, {%8,%9}, {%0,%1,%2,%3};\n"
        : "+f"(d[0]), "+f"(d[1]), "+f"(d[2]), "+f"(d[3])
        : "r"(a[0]), "r"(a[1]), "r"(a[2]), "r"(a[3]), "r"(b[0]), "r"(b[1]));
}
__device__ __forceinline__ void split2(float a, float b, __half2& hi, __half2& lo) {
    __half ha = __float2half_rn(a), hb = __float2half_rn(b);
    hi = __halves2half2(ha, hb);
    lo = __floats2half2_rn(a - __half2float(ha), b - __half2float(hb));
}

// ---------------------------------------------------------------- dtype probe
__global__ void detect_kernel(const int* __restrict__ ei32) {
    if (threadIdx.x == 0 && blockIdx.x == 0) {
        int nz = 0;
        for (int k = 0; k < 64; k++) nz |= ei32[2 * k + 1];
        g_is64 = (nz == 0) ? 1 : 0;
    }
}
__device__ __forceinline__ int load_idx(const void* ei, size_t pos) {
    if (g_is64) return (int)((const long long*)ei)[pos];
    return ((const int*)ei)[pos];
}

// ---------------------------------------------------------------- zero / degree
__global__ void zero_kernel() {
    int i = blockIdx.x * blockDim.x + threadIdx.x;
    if (i < NN) { g_cnt[i] = 0; g_fill[i] = 0; }
}
__global__ void degree_kernel(const void* __restrict__ ei, int E) {
    int e = blockIdx.x * blockDim.x + threadIdx.x;
    if (e < E) {
        int d = load_idx(ei, (size_t)E + e);
        if ((unsigned)d < NN) atomicAdd(&g_cnt[d], 1);
    }
}

// ---------------------------------------------------------------- hierarchical scan
__global__ __launch_bounds__(1024) void scan_partial_kernel() {
    __shared__ int s[1024];
    int tid = threadIdx.x, b = blockIdx.x;
    int i = b * 1024 + tid;
    int v = (i < NN) ? g_cnt[i] : 0;
    if (i < NN) g_inv[i] = 1.0f / fmaxf((float)v, 1.0f);
    s[tid] = v;
    __syncthreads();
#pragma unroll
    for (int off = 1; off < 1024; off <<= 1) {
        int t = (tid >= off) ? s[tid - off] : 0;
        __syncthreads();
        s[tid] += t;
        __syncthreads();
    }
    if (i < NN) g_rowptr[i + 1] = s[tid];
    if (tid == 1023) g_bsum[b] = s[1023];
    if (i == 0) g_rowptr[0] = 0;
}
__global__ void scan_bsum_kernel() {
    __shared__ int s[128];
    int tid = threadIdx.x;
    int v = (tid < NBLK) ? g_bsum[tid] : 0;
    s[tid] = v;
    __syncthreads();
#pragma unroll
    for (int off = 1; off < 128; off <<= 1) {
        int t = (tid >= off) ? s[tid - off] : 0;
        __syncthreads();
        s[tid] += t;
        __syncthreads();
    }
    if (tid < NBLK) g_boff[tid] = s[tid] - v;
}
__global__ __launch_bounds__(1024) void scan_add_kernel() {
    int i = blockIdx.x * 1024 + threadIdx.x;
    if (i < NN) g_rowptr[i + 1] += g_boff[blockIdx.x];
}

// ---------------------------------------------------------------- counting-sort scatter
__global__ void scatter_kernel(const void* __restrict__ ei, int E) {
    int e = blockIdx.x * blockDim.x + threadIdx.x;
    if (e < E) {
        int srcv = load_idx(ei, (size_t)e);
        int d    = load_idx(ei, (size_t)E + e);
        if ((unsigned)d < NN && (unsigned)srcv < NN) {
            int pos = g_rowptr[d] + atomicAdd(&g_fill[d], 1);
            if ((unsigned)pos < EMAX) g_esrc[pos] = srcv;
        }
    }
}

// ---------------------------------------------------------------- aggregate (R10 version: warp per node, fp16 gather, ILP-8)
__global__ __launch_bounds__(256) void aggregate_kernel() {
    int gtid = blockIdx.x * blockDim.x + threadIdx.x;
    int w = gtid >> 5, lane = gtid & 31;
    if (w >= NN) return;
    int beg = g_rowptr[w], end = g_rowptr[w + 1];
    const __half2* __restrict__ base = (const __half2*)g_h16;

    float2 ac[8];
#pragma unroll
    for (int i = 0; i < 8; i++) ac[i] = make_float2(0.f, 0.f);
    int n = end - beg;
    int nfull = n & ~31;
    int j = beg;
    for (; j < beg + nfull; j += 32) {
        int sidx = g_esrc[j + lane];
#pragma unroll
        for (int t = 0; t < 32; t += 8) {
            int sv[8];
#pragma unroll
            for (int u = 0; u < 8; u++) sv[u] = __shfl_sync(0xffffffffu, sidx, t + u);
            float2 v[8];
#pragma unroll
            for (int u = 0; u < 8; u++) v[u] = __half22float2(base[(size_t)sv[u] * 32 + lane]);
#pragma unroll
            for (int u = 0; u < 8; u++) { ac[u].x += v[u].x; ac[u].y += v[u].y; }
        }
    }
    if (j < end) {
        int jl = j + lane;
        int sidx = (jl < end) ? g_esrc[jl] : 0;
        int m = end - j;
        for (int t = 0; t < m; t++) {
            int sv = __shfl_sync(0xffffffffu, sidx, t);
            float2 v = __half22float2(base[(size_t)sv * 32 + lane]);
            ac[0].x += v.x; ac[0].y += v.y;
        }
    }
    float inv = g_inv[w];
    float2 acc = make_float2(0.f, 0.f);
#pragma unroll
    for (int i = 0; i < 8; i++) { acc.x += ac[i].x; acc.y += ac[i].y; }
    acc.x *= inv; acc.y *= inv;
    *(__half2*)(g_agg16 + (size_t)w * HD + lane * 2) = __floats2half2_rn(acc.x, acc.y);
}

// ================================================================ fp16-split MMA GEMMs
#define A2W 36
#define B2W 72

__device__ __forceinline__ void storeA_planes(__half2* Ah, __half2* Al,
                                              const float4* va, int tid) {
#pragma unroll
    for (int it = 0; it < 4; it++) {
        int idx = tid + it * 256;
        int r = idx >> 4, c4 = idx & 15;
        __half2 h0, l0, h1, l1;
        split2(va[it].x, va[it].y, h0, l0);
        split2(va[it].z, va[it].w, h1, l1);
        __half2* ph = Ah + r * A2W + c4 * 2;
        __half2* pl = Al + r * A2W + c4 * 2;
        *(uint2*)ph = make_uint2(*(uint32_t*)&h0, *(uint32_t*)&h1);
        *(uint2*)pl = make_uint2(*(uint32_t*)&l0, *(uint32_t*)&l1);
    }
}
// copy pre-packed fp16 rows straight into the hi smem plane (no ALU)
__device__ __forceinline__ void copyA_hi(__half2* Ah, const __half* hi,
                                         int row0, int tid) {
#pragma unroll
    for (int it = 0; it < 4; it++) {
        int idx = tid + it * 256;
        int r = idx >> 4, c4 = idx & 15;
        int grow = row0 + r;
        uint2 vh = make_uint2(0u, 0u);
        if (grow < NN) vh = *(const uint2*)(hi + (size_t)grow * 64 + c4 * 4);
        *(uint2*)(Ah + r * A2W + c4 * 2) = vh;
    }
}
__device__ __forceinline__ void storeB_planes(__half2* Bh, __half2* Bl,
                                              const float4* vb, int tid) {
    int k2 = tid >> 3, ng = (tid & 7) * 8;
    const float* r0 = (const float*)&vb[0];
    const float* r1 = (const float*)&vb[2];
    __half2 hh[8], ll[8];
#pragma unroll
    for (int jj = 0; jj < 8; jj++) split2(r0[jj], r1[jj], hh[jj], ll[jj]);
    uint4* ph = (uint4*)(Bh + k2 * B2W + ng);
    uint4* pl = (uint4*)(Bl + k2 * B2W + ng);
    ph[0] = make_uint4(*(uint32_t*)&hh[0], *(uint32_t*)&hh[1], *(uint32_t*)&hh[2], *(uint32_t*)&hh[3]);
    ph[1] = make_uint4(*(uint32_t*)&hh[4], *(uint32_t*)&hh[5], *(uint32_t*)&hh[6], *(uint32_t*)&hh[7]);
    pl[0] = make_uint4(*(uint32_t*)&ll[0], *(uint32_t*)&ll[1], *(uint32_t*)&ll[2], *(uint32_t*)&ll[3]);
    pl[1] = make_uint4(*(uint32_t*)&ll[4], *(uint32_t*)&ll[5], *(uint32_t*)&ll[6], *(uint32_t*)&ll[7]);
}

// 3-product kstep (full precision: ah*bh + al*bh + ah*bl)
__device__ __forceinline__ void mma_kstep16(const __half2* Ah, const __half2* Al,
                                            const __half2* Bh, const __half2* Bl,
                                            int m0, int n0, int k2b,
                                            int qrow, int qcol, float acc[4][4]) {
    uint32_t ah[4], al[4];
    int ra = (m0 + qrow) * A2W + k2b + qcol;
    ah[0] = *(const uint32_t*)&Ah[ra];
    ah[1] = *(const uint32_t*)&Ah[ra + 8 * A2W];
    ah[2] = *(const uint32_t*)&Ah[ra + 4];
    ah[3] = *(const uint32_t*)&Ah[ra + 8 * A2W + 4];
    al[0] = *(const uint32_t*)&Al[ra];
    al[1] = *(const uint32_t*)&Al[ra + 8 * A2W];
    al[2] = *(const uint32_t*)&Al[ra + 4];
    al[3] = *(const uint32_t*)&Al[ra + 8 * A2W + 4];
#pragma unroll
    for (int nt = 0; nt < 4; nt++) {
        int nn = n0 + nt * 8;
        int rb = (k2b + qcol) * B2W + nn + qrow;
        uint32_t bh[2], bl2[2];
        bh[0]  = *(const uint32_t*)&Bh[rb];
        bh[1]  = *(const uint32_t*)&Bh[rb + 4 * B2W];
        bl2[0] = *(const uint32_t*)&Bl[rb];
        bl2[1] = *(const uint32_t*)&Bl[rb + 4 * B2W];
        mma_f16(acc[nt], ah, bh);
        mma_f16(acc[nt], al, bh);
        mma_f16(acc[nt], ah, bl2);
    }
}
// 2-product kstep (A hi only: ah*bh + ah*bl) — for fp16 agg chunk
__device__ __forceinline__ void mma_kstep16_hi(const __half2* Ah,
                                               const __half2* Bh, const __half2* Bl,
                                               int m0, int n0, int k2b,
                                               int qrow, int qcol, float acc[4][4]) {
    uint32_t ah[4];
    int ra = (m0 + qrow) * A2W + k2b + qcol;
    ah[0] = *(const uint32_t*)&Ah[ra];
    ah[1] = *(const uint32_t*)&Ah[ra + 8 * A2W];
    ah[2] = *(const uint32_t*)&Ah[ra + 4];
    ah[3] = *(const uint32_t*)&Ah[ra + 8 * A2W + 4];
#pragma unroll
    for (int nt = 0; nt < 4; nt++) {
        int nn = n0 + nt * 8;
        int rb = (k2b + qcol) * B2W + nn + qrow;
        uint32_t bh[2], bl2[2];
        bh[0]  = *(const uint32_t*)&Bh[rb];
        bh[1]  = *(const uint32_t*)&Bh[rb + 4 * B2W];
        bl2[0] = *(const uint32_t*)&Bl[rb];
        bl2[1] = *(const uint32_t*)&Bl[rb + 4 * B2W];
        mma_f16(acc[nt], ah, bh);
        mma_f16(acc[nt], ah, bl2);
    }
}

// ---------------------------------------------------------------- input GEMM: h = x @ Win + b_in
__global__ __launch_bounds__(256) void gemm_in_mma(const float* __restrict__ x,
                                                   const float* __restrict__ Win,
                                                   const float* __restrict__ bin) {
    __shared__ __align__(16) __half2 Ah[64 * A2W], Al[64 * A2W];
    __shared__ __align__(16) __half2 Bh[32 * B2W], Bl[32 * B2W];
    int tid = threadIdx.x;
    int wid = tid >> 5, lane = tid & 31;
    int warpM = wid & 3, warpN = wid >> 2;
    int qrow = lane >> 2, qcol = lane & 3;
    int row0 = blockIdx.x * 64;
    float acc[4][4];
#pragma unroll
    for (int nt = 0; nt < 4; nt++)
#pragma unroll
        for (int i = 0; i < 4; i++) acc[nt][i] = 0.f;

    float4 va[4], vb[4];
    {
        int k2 = tid >> 3, ng = (tid & 7) * 8;
#pragma unroll
        for (int it = 0; it < 4; it++) {
            int idx = tid + it * 256;
            int r = idx >> 4, c4 = idx & 15;
            int grow = row0 + r;
            va[it] = (grow < NN) ? *(const float4*)(x + (size_t)grow * 512 + c4 * 4)
                                 : make_float4(0.f, 0.f, 0.f, 0.f);
        }
        vb[0] = *(const float4*)(Win + (size_t)(2 * k2) * 64 + ng);
        vb[1] = *(const float4*)(Win + (size_t)(2 * k2) * 64 + ng + 4);
        vb[2] = *(const float4*)(Win + (size_t)(2 * k2 + 1) * 64 + ng);
        vb[3] = *(const float4*)(Win + (size_t)(2 * k2 + 1) * 64 + ng + 4);
    }
#pragma unroll 1
    for (int c = 0; c < 8; c++) {
        storeA_planes(Ah, Al, va, tid);
        storeB_planes(Bh, Bl, vb, tid);
        __syncthreads();
        if (c < 7) {
            int kc = (c + 1) * 64;
            int k2 = tid >> 3, ng = (tid & 7) * 8;
#pragma unroll
            for (int it = 0; it < 4; it++) {
                int idx = tid + it * 256;
                int r = idx >> 4, c4 = idx & 15;
                int grow = row0 + r;
                va[it] = (grow < NN) ? *(const float4*)(x + (size_t)grow * 512 + kc + c4 * 4)
                                     : make_float4(0.f, 0.f, 0.f, 0.f);
            }
            vb[0] = *(const float4*)(Win + (size_t)(kc + 2 * k2) * 64 + ng);
            vb[1] = *(const float4*)(Win + (size_t)(kc + 2 * k2) * 64 + ng + 4);
            vb[2] = *(const float4*)(Win + (size_t)(kc + 2 * k2 + 1) * 64 + ng);
            vb[3] = *(const float4*)(Win + (size_t)(kc + 2 * k2 + 1) * 64 + ng + 4);
        }
#pragma unroll
        for (int kk = 0; kk < 4; kk++)
            mma_kstep16(Ah, Al, Bh, Bl, warpM * 16, warpN * 32, kk * 8, qrow, qcol, acc);
        __syncthreads();
    }
#pragma unroll
    for (int nt = 0; nt < 4; nt++) {
        int gc = warpN * 32 + nt * 8 + qcol * 2;
        float2 bv = *(const float2*)(bin + gc);
#pragma unroll
        for (int half = 0; half < 2; half++) {
            int gr = row0 + warpM * 16 + qrow + half * 8;
            if (gr < NN) {
                float2 o;
                o.x = acc[nt][half * 2 + 0] + bv.x;
                o.y = acc[nt][half * 2 + 1] + bv.y;
                *(float2*)(g_h + (size_t)gr * 64 + gc) = o;
                *(__half2*)(g_h16 + (size_t)gr * 64 + gc) = __floats2half2_rn(o.x, o.y);
            }
        }
    }
}

// ---------------------------------------------------------------- layer GEMM:
// h = h + relu(agg @ Wl + bl + h @ Wr); chunk0 = agg16 (hi-only), chunk1 = h (split)
__global__ __launch_bounds__(256) void gemm_layer_mma(const float* __restrict__ Wl,
                                                      const float* __restrict__ Wr,
                                                      const float* __restrict__ bl) {
    __shared__ __align__(16) __half2 Ah[64 * A2W], Al[64 * A2W];
    __shared__ __align__(16) __half2 Bh[32 * B2W], Bl[32 * B2W];
    int tid = threadIdx.x;
    int wid = tid >> 5, lane = tid & 31;
    int warpM = wid & 3, warpN = wid >> 2;
    int qrow = lane >> 2, qcol = lane & 3;
    int row0 = blockIdx.x * 64;
    float acc[4][4];
#pragma unroll
    for (int nt = 0; nt < 4; nt++)
#pragma unroll
        for (int i = 0; i < 4; i++) acc[nt][i] = 0.f;

    // ---- chunk 0: agg16 (hi only) @ Wl
    {
        float4 vb[4];
        int k2 = tid >> 3, ng = (tid & 7) * 8;
        vb[0] = *(const float4*)(Wl + (size_t)(2 * k2) * 64 + ng);
        vb[1] = *(const float4*)(Wl + (size_t)(2 * k2) * 64 + ng + 4);
        vb[2] = *(const float4*)(Wl + (size_t)(2 * k2 + 1) * 64 + ng);
        vb[3] = *(const float4*)(Wl + (size_t)(2 * k2 + 1) * 64 + ng + 4);
        copyA_hi(Ah, g_agg16, row0, tid);
        storeB_planes(Bh, Bl, vb, tid);
        __syncthreads();
#pragma unroll
        for (int kk = 0; kk < 4; kk++)
            mma_kstep16_hi(Ah, Bh, Bl, warpM * 16, warpN * 32, kk * 8, qrow, qcol, acc);
        __syncthreads();
    }
    // ---- chunk 1: h (hi/lo split) @ Wr
    {
        float4 va[4], vb[4];
        int k2 = tid >> 3, ng = (tid & 7) * 8;
#pragma unroll
        for (int it = 0; it < 4; it++) {
            int idx = tid + it * 256;
            int r = idx >> 4, c4 = idx & 15;
            int grow = row0 + r;
            va[it] = (grow < NN) ? *(const float4*)(g_h + (size_t)grow * 64 + c4 * 4)
                                 : make_float4(0.f, 0.f, 0.f, 0.f);
        }
        vb[0] = *(const float4*)(Wr + (size_t)(2 * k2) * 64 + ng);
        vb[1] = *(const float4*)(Wr + (size_t)(2 * k2) * 64 + ng + 4);
        vb[2] = *(const float4*)(Wr + (size_t)(2 * k2 + 1) * 64 + ng);
        vb[3] = *(const float4*)(Wr + (size_t)(2 * k2 + 1) * 64 + ng + 4);
        storeA_planes(Ah, Al, va, tid);
        storeB_planes(Bh, Bl, vb, tid);
        __syncthreads();
#pragma unroll
        for (int kk = 0; kk < 4; kk++)
            mma_kstep16(Ah, Al, Bh, Bl, warpM * 16, warpN * 32, kk * 8, qrow, qcol, acc);
    }
#pragma unroll
    for (int nt = 0; nt < 4; nt++) {
        int gc = warpN * 32 + nt * 8 + qcol * 2;
        float2 bv = *(const float2*)(bl + gc);
#pragma unroll
        for (int half = 0; half < 2; half++) {
            int gr = row0 + warpM * 16 + qrow + half * 8;
            if (gr < NN) {
                float2 old = *(const float2*)(g_h + (size_t)gr * 64 + gc);
                float2 o;
                o.x = old.x + fmaxf(acc[nt][half * 2 + 0] + bv.x, 0.f);
                o.y = old.y + fmaxf(acc[nt][half * 2 + 1] + bv.y, 0.f);
                *(float2*)(g_h + (size_t)gr * 64 + gc) = o;
                *(__half2*)(g_h16 + (size_t)gr * 64 + gc) = __floats2half2_rn(o.x, o.y);
            }
        }
    }
}

// ---------------------------------------------------------------- output GEMM
__global__ __launch_bounds__(256) void gemm_out_mma(const float* __restrict__ Wout,
                                                    const float* __restrict__ bout,
                                                    float* __restrict__ out) {
    __shared__ __align__(16) __half2 Ah[64 * A2W], Al[64 * A2W];
    __shared__ __align__(16) __half2 Bh[32 * B2W], Bl[32 * B2W];
    int tid = threadIdx.x;
    int wid = tid >> 5, lane = tid & 31;
    int warpM = wid & 3, warpN = wid >> 2;
    int qrow = lane >> 2, qcol = lane & 3;
    int row0 = blockIdx.x * 64;
    int col0 = blockIdx.y * 64;
    float acc[4][4];
#pragma unroll
    for (int nt = 0; nt < 4; nt++)
#pragma unroll
        for (int i = 0; i < 4; i++) acc[nt][i] = 0.f;

    {
        float4 va[4], vb[4];
        int k2 = tid >> 3, ng = (tid & 7) * 8;
#pragma unroll
        for (int it = 0; it < 4; it++) {
            int idx = tid + it * 256;
            int r = idx >> 4, c4 = idx & 15;
            int grow = row0 + r;
            va[it] = (grow < NN) ? *(const float4*)(g_h + (size_t)grow * 64 + c4 * 4)
                                 : make_float4(0.f, 0.f, 0.f, 0.f);
        }
        vb[0] = *(const float4*)(Wout + (size_t)(2 * k2) * 256 + col0 + ng);
        vb[1] = *(const float4*)(Wout + (size_t)(2 * k2) * 256 + col0 + ng + 4);
        vb[2] = *(const float4*)(Wout + (size_t)(2 * k2 + 1) * 256 + col0 + ng);
        vb[3] = *(const float4*)(Wout + (size_t)(2 * k2 + 1) * 256 + col0 + ng + 4);
        storeA_planes(Ah, Al, va, tid);
        storeB_planes(Bh, Bl, vb, tid);
    }
    __syncthreads();
#pragma unroll
    for (int kk = 0; kk < 4; kk++)
        mma_kstep16(Ah, Al, Bh, Bl, warpM * 16, warpN * 32, kk * 8, qrow, qcol, acc);

#pragma unroll
    for (int nt = 0; nt < 4; nt++) {
        int gc = warpN * 32 + nt * 8 + qcol * 2;
        float2 bv = *(const float2*)(bout + col0 + gc);
#pragma unroll
        for (int half = 0; half < 2; half++) {
            int gr = row0 + warpM * 16 + qrow + half * 8;
            if (gr < NN) {
                float2 o;
                o.x = acc[nt][half * 2 + 0] + bv.x;
                o.y = acc[nt][half * 2 + 1] + bv.y;
                *(float2*)(out + (size_t)gr * 256 + col0 + gc) = o;
            }
        }
    }
}

// ---------------------------------------------------------------- launch
extern "C" void kernel_launch(void* const* d_in, const int* in_sizes, int n_in,
                              void* d_out, int out_size) {
    const float* x    = (const float*)d_in[0];
    const void*  ei   = d_in[1];
    const float* Win  = (const float*)d_in[2];
    const float* bin  = (const float*)d_in[3];
    const float* Wl   = (const float*)d_in[4];
    const float* bl   = (const float*)d_in[5];
    const float* Wr   = (const float*)d_in[6];
    const float* Wout = (const float*)d_in[7];
    const float* bout = (const float*)d_in[8];
    float* out = (float*)d_out;
    int E = in_sizes[1] / 2;

    static cudaStream_t s_side = nullptr;
    static cudaEvent_t  e_fork = nullptr, e_join = nullptr;
    if (s_side == nullptr) {
        cudaStreamCreateWithFlags(&s_side, cudaStreamNonBlocking);
        cudaEventCreateWithFlags(&e_fork, cudaEventDisableTiming);
        cudaEventCreateWithFlags(&e_join, cudaEventDisableTiming);
    }

    cudaEventRecord(e_fork, 0);
    cudaStreamWaitEvent(s_side, e_fork, 0);

    // ---- side stream: CSR build chain (edge_index only)
    detect_kernel<<<1, 32, 0, s_side>>>((const int*)ei);
    zero_kernel<<<(NN + 255) / 256, 256, 0, s_side>>>();
    degree_kernel<<<(E + 255) / 256, 256, 0, s_side>>>(ei, E);
    scan_partial_kernel<<<NBLK, 1024, 0, s_side>>>();
    scan_bsum_kernel<<<1, 128, 0, s_side>>>();
    scan_add_kernel<<<NBLK, 1024, 0, s_side>>>();
    scatter_kernel<<<(E + 255) / 256, 256, 0, s_side>>>(ei, E);
    cudaEventRecord(e_join, s_side);

    // ---- main stream: input GEMM — overlaps CSR build
    gemm_in_mma<<<MBLK, 256>>>(x, Win, bin);

    cudaStreamWaitEvent(0, e_join, 0);

    for (int i = 0; i < 4; i++) {
        aggregate_kernel<<<(NN * 32 + 255) / 256, 256>>>();
        gemm_layer_mma<<<MBLK, 256>>>(Wl + i * HD * HD, Wr + i * HD * HD, bl + i * HD);
    }

    gemm_out_mma<<<dim3(MBLK, 4), 256>>>(Wout, bout, out);
}

// round 15
// speedup vs baseline: 1.2855x; 1.0444x over previous
#include <cuda_runtime.h>
#include <cuda_fp16.h>
#include <cstdint>

#define NN   100000
#define HD   64
#define EMAX 3200000
#define NBLK ((NN + 1023) / 1024)   // 98
#define MBLK ((NN + 63) / 64)       // 1563

// ---- scratch (device globals; no allocation allowed) ----
__device__ __align__(16) float  g_h[NN * HD];      // node features fp32 (25.6 MB)
__device__ __align__(16) __half g_h16[NN * HD];    // fp16 mirror for gather (12.8 MB)
__device__ __align__(16) __half g_agg16[NN * HD];  // aggregated neighbors, fp16 (12.8 MB)
__device__ int   g_cnt[NN];
__device__ float g_inv[NN];
__device__ int   g_rowptr[NN + 1];
__device__ int   g_fill[NN];
__device__ int   g_esrc[EMAX];
__device__ int   g_is64;
__device__ int   g_bsum[NBLK];
__device__ int   g_boff[NBLK];

// ---------------------------------------------------------------- fp16 split mma helpers
__device__ __forceinline__ void mma_f16(float* d, const uint32_t* a, const uint32_t* b) {
    asm volatile(
        "mma.sync.aligned.m16n8k16.row.col.f32.f16.f16.f32 "
        "{%0,%1,%2,%3}, {%4,%5,%6,%7}, {%8,%9}, {%0,%1,%2,%3};\n"
        : "+f"(d[0]), "+f"(d[1]), "+f"(d[2]), "+f"(d[3])
        : "r"(a[0]), "r"(a[1]), "r"(a[2]), "r"(a[3]), "r"(b[0]), "r"(b[1]));
}
__device__ __forceinline__ void split2(float a, float b, __half2& hi, __half2& lo) {
    __half ha = __float2half_rn(a), hb = __float2half_rn(b);
    hi = __halves2half2(ha, hb);
    lo = __floats2half2_rn(a - __half2float(ha), b - __half2float(hb));
}

// ---------------------------------------------------------------- dtype probe
__global__ void detect_kernel(const int* __restrict__ ei32) {
    if (threadIdx.x == 0 && blockIdx.x == 0) {
        int nz = 0;
        for (int k = 0; k < 64; k++) nz |= ei32[2 * k + 1];
        g_is64 = (nz == 0) ? 1 : 0;
    }
}
__device__ __forceinline__ int load_idx(const void* ei, size_t pos) {
    if (g_is64) return (int)((const long long*)ei)[pos];
    return ((const int*)ei)[pos];
}

// ---------------------------------------------------------------- zero / degree
__global__ void zero_kernel() {
    int i = blockIdx.x * blockDim.x + threadIdx.x;
    if (i < NN) { g_cnt[i] = 0; g_fill[i] = 0; }
}
__global__ void degree_kernel(const void* __restrict__ ei, int E) {
    int e = blockIdx.x * blockDim.x + threadIdx.x;
    if (e < E) {
        int d = load_idx(ei, (size_t)E + e);
        if ((unsigned)d < NN) atomicAdd(&g_cnt[d], 1);
    }
}

// ---------------------------------------------------------------- hierarchical scan
__global__ __launch_bounds__(1024) void scan_partial_kernel() {
    __shared__ int s[1024];
    int tid = threadIdx.x, b = blockIdx.x;
    int i = b * 1024 + tid;
    int v = (i < NN) ? g_cnt[i] : 0;
    if (i < NN) g_inv[i] = 1.0f / fmaxf((float)v, 1.0f);
    s[tid] = v;
    __syncthreads();
#pragma unroll
    for (int off = 1; off < 1024; off <<= 1) {
        int t = (tid >= off) ? s[tid - off] : 0;
        __syncthreads();
        s[tid] += t;
        __syncthreads();
    }
    if (i < NN) g_rowptr[i + 1] = s[tid];
    if (tid == 1023) g_bsum[b] = s[1023];
    if (i == 0) g_rowptr[0] = 0;
}
__global__ void scan_bsum_kernel() {
    __shared__ int s[128];
    int tid = threadIdx.x;
    int v = (tid < NBLK) ? g_bsum[tid] : 0;
    s[tid] = v;
    __syncthreads();
#pragma unroll
    for (int off = 1; off < 128; off <<= 1) {
        int t = (tid >= off) ? s[tid - off] : 0;
        __syncthreads();
        s[tid] += t;
        __syncthreads();
    }
    if (tid < NBLK) g_boff[tid] = s[tid] - v;
}
__global__ __launch_bounds__(1024) void scan_add_kernel() {
    int i = blockIdx.x * 1024 + threadIdx.x;
    if (i < NN) g_rowptr[i + 1] += g_boff[blockIdx.x];
}

// ---------------------------------------------------------------- counting-sort scatter
__global__ void scatter_kernel(const void* __restrict__ ei, int E) {
    int e = blockIdx.x * blockDim.x + threadIdx.x;
    if (e < E) {
        int srcv = load_idx(ei, (size_t)e);
        int d    = load_idx(ei, (size_t)E + e);
        if ((unsigned)d < NN && (unsigned)srcv < NN) {
            int pos = g_rowptr[d] + atomicAdd(&g_fill[d], 1);
            if ((unsigned)pos < EMAX) g_esrc[pos] = srcv;
        }
    }
}

// ---------------------------------------------------------------- aggregate (warp per node, fp16 gather, ILP-8)
__global__ __launch_bounds__(256) void aggregate_kernel() {
    int gtid = blockIdx.x * blockDim.x + threadIdx.x;
    int w = gtid >> 5, lane = gtid & 31;
    if (w >= NN) return;
    int beg = g_rowptr[w], end = g_rowptr[w + 1];
    const __half2* __restrict__ base = (const __half2*)g_h16;

    float2 ac[8];
#pragma unroll
    for (int i = 0; i < 8; i++) ac[i] = make_float2(0.f, 0.f);
    int n = end - beg;
    int nfull = n & ~31;
    int j = beg;
    for (; j < beg + nfull; j += 32) {
        int sidx = g_esrc[j + lane];
#pragma unroll
        for (int t = 0; t < 32; t += 8) {
            int sv[8];
#pragma unroll
            for (int u = 0; u < 8; u++) sv[u] = __shfl_sync(0xffffffffu, sidx, t + u);
            float2 v[8];
#pragma unroll
            for (int u = 0; u < 8; u++) v[u] = __half22float2(base[(size_t)sv[u] * 32 + lane]);
#pragma unroll
            for (int u = 0; u < 8; u++) { ac[u].x += v[u].x; ac[u].y += v[u].y; }
        }
    }
    if (j < end) {
        int jl = j + lane;
        int sidx = (jl < end) ? g_esrc[jl] : 0;
        int m = end - j;
        for (int t = 0; t < m; t++) {
            int sv = __shfl_sync(0xffffffffu, sidx, t);
            float2 v = __half22float2(base[(size_t)sv * 32 + lane]);
            ac[0].x += v.x; ac[0].y += v.y;
        }
    }
    float inv = g_inv[w];
    float2 acc = make_float2(0.f, 0.f);
#pragma unroll
    for (int i = 0; i < 8; i++) { acc.x += ac[i].x; acc.y += ac[i].y; }
    acc.x *= inv; acc.y *= inv;
    *(__half2*)(g_agg16 + (size_t)w * HD + lane * 2) = __floats2half2_rn(acc.x, acc.y);
}

// ================================================================ fp16-split MMA GEMMs
#define A2W 36
#define B2W 72

__device__ __forceinline__ void storeA_planes(__half2* Ah, __half2* Al,
                                              const float4* va, int tid) {
#pragma unroll
    for (int it = 0; it < 4; it++) {
        int idx = tid + it * 256;
        int r = idx >> 4, c4 = idx & 15;
        __half2 h0, l0, h1, l1;
        split2(va[it].x, va[it].y, h0, l0);
        split2(va[it].z, va[it].w, h1, l1);
        __half2* ph = Ah + r * A2W + c4 * 2;
        __half2* pl = Al + r * A2W + c4 * 2;
        *(uint2*)ph = make_uint2(*(uint32_t*)&h0, *(uint32_t*)&h1);
        *(uint2*)pl = make_uint2(*(uint32_t*)&l0, *(uint32_t*)&l1);
    }
}
// copy pre-packed fp16 rows straight into the hi smem plane (no ALU)
__device__ __forceinline__ void copyA_hi(__half2* Ah, const __half* hi,
                                         int row0, int tid) {
#pragma unroll
    for (int it = 0; it < 4; it++) {
        int idx = tid + it * 256;
        int r = idx >> 4, c4 = idx & 15;
        int grow = row0 + r;
        uint2 vh = make_uint2(0u, 0u);
        if (grow < NN) vh = *(const uint2*)(hi + (size_t)grow * 64 + c4 * 4);
        *(uint2*)(Ah + r * A2W + c4 * 2) = vh;
    }
}
__device__ __forceinline__ void storeB_planes(__half2* Bh, __half2* Bl,
                                              const float4* vb, int tid) {
    int k2 = tid >> 3, ng = (tid & 7) * 8;
    const float* r0 = (const float*)&vb[0];
    const float* r1 = (const float*)&vb[2];
    __half2 hh[8], ll[8];
#pragma unroll
    for (int jj = 0; jj < 8; jj++) split2(r0[jj], r1[jj], hh[jj], ll[jj]);
    uint4* ph = (uint4*)(Bh + k2 * B2W + ng);
    uint4* pl = (uint4*)(Bl + k2 * B2W + ng);
    ph[0] = make_uint4(*(uint32_t*)&hh[0], *(uint32_t*)&hh[1], *(uint32_t*)&hh[2], *(uint32_t*)&hh[3]);
    ph[1] = make_uint4(*(uint32_t*)&hh[4], *(uint32_t*)&hh[5], *(uint32_t*)&hh[6], *(uint32_t*)&hh[7]);
    pl[0] = make_uint4(*(uint32_t*)&ll[0], *(uint32_t*)&ll[1], *(uint32_t*)&ll[2], *(uint32_t*)&ll[3]);
    pl[1] = make_uint4(*(uint32_t*)&ll[4], *(uint32_t*)&ll[5], *(uint32_t*)&ll[6], *(uint32_t*)&ll[7]);
}
// hi-only B stage (fp16-rounded weights; no residual plane)
__device__ __forceinline__ void storeB_hi(__half2* Bh, const float4* vb, int tid) {
    int k2 = tid >> 3, ng = (tid & 7) * 8;
    const float* r0 = (const float*)&vb[0];
    const float* r1 = (const float*)&vb[2];
    __half2 hh[8];
#pragma unroll
    for (int jj = 0; jj < 8; jj++) hh[jj] = __floats2half2_rn(r0[jj], r1[jj]);
    uint4* ph = (uint4*)(Bh + k2 * B2W + ng);
    ph[0] = make_uint4(*(uint32_t*)&hh[0], *(uint32_t*)&hh[1], *(uint32_t*)&hh[2], *(uint32_t*)&hh[3]);
    ph[1] = make_uint4(*(uint32_t*)&hh[4], *(uint32_t*)&hh[5], *(uint32_t*)&hh[6], *(uint32_t*)&hh[7]);
}

// 3-product kstep (full precision: ah*bh + al*bh + ah*bl)
__device__ __forceinline__ void mma_kstep16(const __half2* Ah, const __half2* Al,
                                            const __half2* Bh, const __half2* Bl,
                                            int m0, int n0, int k2b,
                                            int qrow, int qcol, float acc[4][4]) {
    uint32_t ah[4], al[4];
    int ra = (m0 + qrow) * A2W + k2b + qcol;
    ah[0] = *(const uint32_t*)&Ah[ra];
    ah[1] = *(const uint32_t*)&Ah[ra + 8 * A2W];
    ah[2] = *(const uint32_t*)&Ah[ra + 4];
    ah[3] = *(const uint32_t*)&Ah[ra + 8 * A2W + 4];
    al[0] = *(const uint32_t*)&Al[ra];
    al[1] = *(const uint32_t*)&Al[ra + 8 * A2W];
    al[2] = *(const uint32_t*)&Al[ra + 4];
    al[3] = *(const uint32_t*)&Al[ra + 8 * A2W + 4];
#pragma unroll
    for (int nt = 0; nt < 4; nt++) {
        int nn = n0 + nt * 8;
        int rb = (k2b + qcol) * B2W + nn + qrow;
        uint32_t bh[2], bl2[2];
        bh[0]  = *(const uint32_t*)&Bh[rb];
        bh[1]  = *(const uint32_t*)&Bh[rb + 4 * B2W];
        bl2[0] = *(const uint32_t*)&Bl[rb];
        bl2[1] = *(const uint32_t*)&Bl[rb + 4 * B2W];
        mma_f16(acc[nt], ah, bh);
        mma_f16(acc[nt], al, bh);
        mma_f16(acc[nt], ah, bl2);
    }
}
// 2-product kstep, A split / B hi-only: (ah+al)*bh — exact x, fp16 weights
__device__ __forceinline__ void mma_kstep16_xsplit(const __half2* Ah, const __half2* Al,
                                                   const __half2* Bh,
                                                   int m0, int n0, int k2b,
                                                   int qrow, int qcol, float acc[4][4]) {
    uint32_t ah[4], al[4];
    int ra = (m0 + qrow) * A2W + k2b + qcol;
    ah[0] = *(const uint32_t*)&Ah[ra];
    ah[1] = *(const uint32_t*)&Ah[ra + 8 * A2W];
    ah[2] = *(const uint32_t*)&Ah[ra + 4];
    ah[3] = *(const uint32_t*)&Ah[ra + 8 * A2W + 4];
    al[0] = *(const uint32_t*)&Al[ra];
    al[1] = *(const uint32_t*)&Al[ra + 8 * A2W];
    al[2] = *(const uint32_t*)&Al[ra + 4];
    al[3] = *(const uint32_t*)&Al[ra + 8 * A2W + 4];
#pragma unroll
    for (int nt = 0; nt < 4; nt++) {
        int nn = n0 + nt * 8;
        int rb = (k2b + qcol) * B2W + nn + qrow;
        uint32_t bh[2];
        bh[0] = *(const uint32_t*)&Bh[rb];
        bh[1] = *(const uint32_t*)&Bh[rb + 4 * B2W];
        mma_f16(acc[nt], ah, bh);
        mma_f16(acc[nt], al, bh);
    }
}
// 2-product kstep (A hi only: ah*bh + ah*bl) — for fp16 agg chunk
__device__ __forceinline__ void mma_kstep16_hi(const __half2* Ah,
                                               const __half2* Bh, const __half2* Bl,
                                               int m0, int n0, int k2b,
                                               int qrow, int qcol, float acc[4][4]) {
    uint32_t ah[4];
    int ra = (m0 + qrow) * A2W + k2b + qcol;
    ah[0] = *(const uint32_t*)&Ah[ra];
    ah[1] = *(const uint32_t*)&Ah[ra + 8 * A2W];
    ah[2] = *(const uint32_t*)&Ah[ra + 4];
    ah[3] = *(const uint32_t*)&Ah[ra + 8 * A2W + 4];
#pragma unroll
    for (int nt = 0; nt < 4; nt++) {
        int nn = n0 + nt * 8;
        int rb = (k2b + qcol) * B2W + nn + qrow;
        uint32_t bh[2], bl2[2];
        bh[0]  = *(const uint32_t*)&Bh[rb];
        bh[1]  = *(const uint32_t*)&Bh[rb + 4 * B2W];
        bl2[0] = *(const uint32_t*)&Bl[rb];
        bl2[1] = *(const uint32_t*)&Bl[rb + 4 * B2W];
        mma_f16(acc[nt], ah, bh);
        mma_f16(acc[nt], ah, bl2);
    }
}

// ---------------------------------------------------------------- input GEMM: h = x @ Win_fp16 + b_in
// x kept exactly (hi/lo split); Win rounded to fp16 — 2 products per kstep.
__global__ __launch_bounds__(256) void gemm_in_mma(const float* __restrict__ x,
                                                   const float* __restrict__ Win,
                                                   const float* __restrict__ bin) {
    __shared__ __align__(16) __half2 Ah[64 * A2W], Al[64 * A2W];
    __shared__ __align__(16) __half2 Bh[32 * B2W];
    int tid = threadIdx.x;
    int wid = tid >> 5, lane = tid & 31;
    int warpM = wid & 3, warpN = wid >> 2;
    int qrow = lane >> 2, qcol = lane & 3;
    int row0 = blockIdx.x * 64;
    float acc[4][4];
#pragma unroll
    for (int nt = 0; nt < 4; nt++)
#pragma unroll
        for (int i = 0; i < 4; i++) acc[nt][i] = 0.f;

    float4 va[4], vb[4];
    {
        int k2 = tid >> 3, ng = (tid & 7) * 8;
#pragma unroll
        for (int it = 0; it < 4; it++) {
            int idx = tid + it * 256;
            int r = idx >> 4, c4 = idx & 15;
            int grow = row0 + r;
            va[it] = (grow < NN) ? *(const float4*)(x + (size_t)grow * 512 + c4 * 4)
                                 : make_float4(0.f, 0.f, 0.f, 0.f);
        }
        vb[0] = *(const float4*)(Win + (size_t)(2 * k2) * 64 + ng);
        vb[1] = *(const float4*)(Win + (size_t)(2 * k2) * 64 + ng + 4);
        vb[2] = *(const float4*)(Win + (size_t)(2 * k2 + 1) * 64 + ng);
        vb[3] = *(const float4*)(Win + (size_t)(2 * k2 + 1) * 64 + ng + 4);
    }
#pragma unroll 1
    for (int c = 0; c < 8; c++) {
        storeA_planes(Ah, Al, va, tid);
        storeB_hi(Bh, vb, tid);
        __syncthreads();
        if (c < 7) {
            int kc = (c + 1) * 64;
            int k2 = tid >> 3, ng = (tid & 7) * 8;
#pragma unroll
            for (int it = 0; it < 4; it++) {
                int idx = tid + it * 256;
                int r = idx >> 4, c4 = idx & 15;
                int grow = row0 + r;
                va[it] = (grow < NN) ? *(const float4*)(x + (size_t)grow * 512 + kc + c4 * 4)
                                     : make_float4(0.f, 0.f, 0.f, 0.f);
            }
            vb[0] = *(const float4*)(Win + (size_t)(kc + 2 * k2) * 64 + ng);
            vb[1] = *(const float4*)(Win + (size_t)(kc + 2 * k2) * 64 + ng + 4);
            vb[2] = *(const float4*)(Win + (size_t)(kc + 2 * k2 + 1) * 64 + ng);
            vb[3] = *(const float4*)(Win + (size_t)(kc + 2 * k2 + 1) * 64 + ng + 4);
        }
#pragma unroll
        for (int kk = 0; kk < 4; kk++)
            mma_kstep16_xsplit(Ah, Al, Bh, warpM * 16, warpN * 32, kk * 8, qrow, qcol, acc);
        __syncthreads();
    }
#pragma unroll
    for (int nt = 0; nt < 4; nt++) {
        int gc = warpN * 32 + nt * 8 + qcol * 2;
        float2 bv = *(const float2*)(bin + gc);
#pragma unroll
        for (int half = 0; half < 2; half++) {
            int gr = row0 + warpM * 16 + qrow + half * 8;
            if (gr < NN) {
                float2 o;
                o.x = acc[nt][half * 2 + 0] + bv.x;
                o.y = acc[nt][half * 2 + 1] + bv.y;
                *(float2*)(g_h + (size_t)gr * 64 + gc) = o;
                *(__half2*)(g_h16 + (size_t)gr * 64 + gc) = __floats2half2_rn(o.x, o.y);
            }
        }
    }
}

// ---------------------------------------------------------------- layer GEMM:
// h = h + relu(agg @ Wl + bl + h @ Wr); chunk0 = agg16 (hi-only), chunk1 = h (split)
__global__ __launch_bounds__(256) void gemm_layer_mma(const float* __restrict__ Wl,
                                                      const float* __restrict__ Wr,
                                                      const float* __restrict__ bl) {
    __shared__ __align__(16) __half2 Ah[64 * A2W], Al[64 * A2W];
    __shared__ __align__(16) __half2 Bh[32 * B2W], Bl[32 * B2W];
    int tid = threadIdx.x;
    int wid = tid >> 5, lane = tid & 31;
    int warpM = wid & 3, warpN = wid >> 2;
    int qrow = lane >> 2, qcol = lane & 3;
    int row0 = blockIdx.x * 64;
    float acc[4][4];
#pragma unroll
    for (int nt = 0; nt < 4; nt++)
#pragma unroll
        for (int i = 0; i < 4; i++) acc[nt][i] = 0.f;

    // ---- chunk 0: agg16 (hi only) @ Wl
    {
        float4 vb[4];
        int k2 = tid >> 3, ng = (tid & 7) * 8;
        vb[0] = *(const float4*)(Wl + (size_t)(2 * k2) * 64 + ng);
        vb[1] = *(const float4*)(Wl + (size_t)(2 * k2) * 64 + ng + 4);
        vb[2] = *(const float4*)(Wl + (size_t)(2 * k2 + 1) * 64 + ng);
        vb[3] = *(const float4*)(Wl + (size_t)(2 * k2 + 1) * 64 + ng + 4);
        copyA_hi(Ah, g_agg16, row0, tid);
        storeB_planes(Bh, Bl, vb, tid);
        __syncthreads();
#pragma unroll
        for (int kk = 0; kk < 4; kk++)
            mma_kstep16_hi(Ah, Bh, Bl, warpM * 16, warpN * 32, kk * 8, qrow, qcol, acc);
        __syncthreads();
    }
    // ---- chunk 1: h (hi/lo split) @ Wr
    {
        float4 va[4], vb[4];
        int k2 = tid >> 3, ng = (tid & 7) * 8;
#pragma unroll
        for (int it = 0; it < 4; it++) {
            int idx = tid + it * 256;
            int r = idx >> 4, c4 = idx & 15;
            int grow = row0 + r;
            va[it] = (grow < NN) ? *(const float4*)(g_h + (size_t)grow * 64 + c4 * 4)
                                 : make_float4(0.f, 0.f, 0.f, 0.f);
        }
        vb[0] = *(const float4*)(Wr + (size_t)(2 * k2) * 64 + ng);
        vb[1] = *(const float4*)(Wr + (size_t)(2 * k2) * 64 + ng + 4);
        vb[2] = *(const float4*)(Wr + (size_t)(2 * k2 + 1) * 64 + ng);
        vb[3] = *(const float4*)(Wr + (size_t)(2 * k2 + 1) * 64 + ng + 4);
        storeA_planes(Ah, Al, va, tid);
        storeB_planes(Bh, Bl, vb, tid);
        __syncthreads();
#pragma unroll
        for (int kk = 0; kk < 4; kk++)
            mma_kstep16(Ah, Al, Bh, Bl, warpM * 16, warpN * 32, kk * 8, qrow, qcol, acc);
    }
#pragma unroll
    for (int nt = 0; nt < 4; nt++) {
        int gc = warpN * 32 + nt * 8 + qcol * 2;
        float2 bv = *(const float2*)(bl + gc);
#pragma unroll
        for (int half = 0; half < 2; half++) {
            int gr = row0 + warpM * 16 + qrow + half * 8;
            if (gr < NN) {
                float2 old = *(const float2*)(g_h + (size_t)gr * 64 + gc);
                float2 o;
                o.x = old.x + fmaxf(acc[nt][half * 2 + 0] + bv.x, 0.f);
                o.y = old.y + fmaxf(acc[nt][half * 2 + 1] + bv.y, 0.f);
                *(float2*)(g_h + (size_t)gr * 64 + gc) = o;
                *(__half2*)(g_h16 + (size_t)gr * 64 + gc) = __floats2half2_rn(o.x, o.y);
            }
        }
    }
}

// ---------------------------------------------------------------- output GEMM
__global__ __launch_bounds__(256) void gemm_out_mma(const float* __restrict__ Wout,
                                                    const float* __restrict__ bout,
                                                    float* __restrict__ out) {
    __shared__ __align__(16) __half2 Ah[64 * A2W], Al[64 * A2W];
    __shared__ __align__(16) __half2 Bh[32 * B2W], Bl[32 * B2W];
    int tid = threadIdx.x;
    int wid = tid >> 5, lane = tid & 31;
    int warpM = wid & 3, warpN = wid >> 2;
    int qrow = lane >> 2, qcol = lane & 3;
    int row0 = blockIdx.x * 64;
    int col0 = blockIdx.y * 64;
    float acc[4][4];
#pragma unroll
    for (int nt = 0; nt < 4; nt++)
#pragma unroll
        for (int i = 0; i < 4; i++) acc[nt][i] = 0.f;

    {
        float4 va[4], vb[4];
        int k2 = tid >> 3, ng = (tid & 7) * 8;
#pragma unroll
        for (int it = 0; it < 4; it++) {
            int idx = tid + it * 256;
            int r = idx >> 4, c4 = idx & 15;
            int grow = row0 + r;
            va[it] = (grow < NN) ? *(const float4*)(g_h + (size_t)grow * 64 + c4 * 4)
                                 : make_float4(0.f, 0.f, 0.f, 0.f);
        }
        vb[0] = *(const float4*)(Wout + (size_t)(2 * k2) * 256 + col0 + ng);
        vb[1] = *(const float4*)(Wout + (size_t)(2 * k2) * 256 + col0 + ng + 4);
        vb[2] = *(const float4*)(Wout + (size_t)(2 * k2 + 1) * 256 + col0 + ng);
        vb[3] = *(const float4*)(Wout + (size_t)(2 * k2 + 1) * 256 + col0 + ng + 4);
        storeA_planes(Ah, Al, va, tid);
        storeB_planes(Bh, Bl, vb, tid);
    }
    __syncthreads();
#pragma unroll
    for (int kk = 0; kk < 4; kk++)
        mma_kstep16(Ah, Al, Bh, Bl, warpM * 16, warpN * 32, kk * 8, qrow, qcol, acc);

#pragma unroll
    for (int nt = 0; nt < 4; nt++) {
        int gc = warpN * 32 + nt * 8 + qcol * 2;
        float2 bv = *(const float2*)(bout + col0 + gc);
#pragma unroll
        for (int half = 0; half < 2; half++) {
            int gr = row0 + warpM * 16 + qrow + half * 8;
            if (gr < NN) {
                float2 o;
                o.x = acc[nt][half * 2 + 0] + bv.x;
                o.y = acc[nt][half * 2 + 1] + bv.y;
                *(float2*)(out + (size_t)gr * 256 + col0 + gc) = o;
            }
        }
    }
}

// ---------------------------------------------------------------- launch
extern "C" void kernel_launch(void* const* d_in, const int* in_sizes, int n_in,
                              void* d_out, int out_size) {
    const float* x    = (const float*)d_in[0];
    const void*  ei   = d_in[1];
    const float* Win  = (const float*)d_in[2];
    const float* bin  = (const float*)d_in[3];
    const float* Wl   = (const float*)d_in[4];
    const float* bl   = (const float*)d_in[5];
    const float* Wr   = (const float*)d_in[6];
    const float* Wout = (const float*)d_in[7];
    const float* bout = (const float*)d_in[8];
    float* out = (float*)d_out;
    int E = in_sizes[1] / 2;

    static cudaStream_t s_side = nullptr;
    static cudaEvent_t  e_fork = nullptr, e_join = nullptr;
    if (s_side == nullptr) {
        cudaStreamCreateWithFlags(&s_side, cudaStreamNonBlocking);
        cudaEventCreateWithFlags(&e_fork, cudaEventDisableTiming);
        cudaEventCreateWithFlags(&e_join, cudaEventDisableTiming);
    }

    cudaEventRecord(e_fork, 0);
    cudaStreamWaitEvent(s_side, e_fork, 0);

    // ---- side stream: CSR build chain (edge_index only)
    detect_kernel<<<1, 32, 0, s_side>>>((const int*)ei);
    zero_kernel<<<(NN + 255) / 256, 256, 0, s_side>>>();
    degree_kernel<<<(E + 255) / 256, 256, 0, s_side>>>(ei, E);
    scan_partial_kernel<<<NBLK, 1024, 0, s_side>>>();
    scan_bsum_kernel<<<1, 128, 0, s_side>>>();
    scan_add_kernel<<<NBLK, 1024, 0, s_side>>>();
    scatter_kernel<<<(E + 255) / 256, 256, 0, s_side>>>(ei, E);
    cudaEventRecord(e_join, s_side);

    // ---- main stream: input GEMM — overlaps CSR build
    gemm_in_mma<<<MBLK, 256>>>(x, Win, bin);

    cudaStreamWaitEvent(0, e_join, 0);

    for (int i = 0; i < 4; i++) {
        aggregate_kernel<<<(NN * 32 + 255) / 256, 256>>>();
        gemm_layer_mma<<<MBLK, 256>>>(Wl + i * HD * HD, Wr + i * HD * HD, bl + i * HD);
    }

    gemm_out_mma<<<dim3(MBLK, 4), 256>>>(Wout, bout, out);
}

// round 16
// speedup vs baseline: 1.3460x; 1.0471x over previous
#include <cuda_runtime.h>
#include <cuda_fp16.h>
#include <cstdint>

#define NN   100000
#define HD   64
#define EMAX 3200000
#define NBLK ((NN + 1023) / 1024)   // 98
#define MBLK ((NN + 63) / 64)       // 1563

// ---- scratch (device globals; no allocation allowed) ----
__device__ __align__(16) float  g_h[NN * HD];      // node features fp32 (25.6 MB)
__device__ __align__(16) __half g_h16[NN * HD];    // fp16 mirror for gather (12.8 MB)
__device__ __align__(16) __half g_agg16[NN * HD];  // aggregated neighbors, fp16 (12.8 MB)
__device__ int   g_cnt[NN];
__device__ float g_inv[NN];
__device__ int   g_rowptr[NN + 1];
__device__ int   g_fill[NN];
__device__ int   g_esrc[EMAX];
__device__ int   g_is64;
__device__ int   g_bsum[NBLK];
__device__ int   g_boff[NBLK];

// ---------------------------------------------------------------- fp16 split mma helpers
__device__ __forceinline__ void mma_f16(float* d, const uint32_t* a, const uint32_t* b) {
    asm volatile(
        "mma.sync.aligned.m16n8k16.row.col.f32.f16.f16.f32 "
        "{%0,%1,%2,%3}, {%4,%5,%6,%7}, {%8,%9}, {%0,%1,%2,%3};\n"
        : "+f"(d[0]), "+f"(d[1]), "+f"(d[2]), "+f"(d[3])
        : "r"(a[0]), "r"(a[1]), "r"(a[2]), "r"(a[3]), "r"(b[0]), "r"(b[1]));
}
__device__ __forceinline__ void split2(float a, float b, __half2& hi, __half2& lo) {
    __half ha = __float2half_rn(a), hb = __float2half_rn(b);
    hi = __halves2half2(ha, hb);
    lo = __floats2half2_rn(a - __half2float(ha), b - __half2float(hb));
}

// ---------------------------------------------------------------- dtype probe
__global__ void detect_kernel(const int* __restrict__ ei32) {
    if (threadIdx.x == 0 && blockIdx.x == 0) {
        int nz = 0;
        for (int k = 0; k < 64; k++) nz |= ei32[2 * k + 1];
        g_is64 = (nz == 0) ? 1 : 0;
    }
}
__device__ __forceinline__ int load_idx(const void* ei, size_t pos) {
    if (g_is64) return (int)((const long long*)ei)[pos];
    return ((const int*)ei)[pos];
}

// ---------------------------------------------------------------- zero / degree
__global__ void zero_kernel() {
    int i = blockIdx.x * blockDim.x + threadIdx.x;
    if (i < NN) { g_cnt[i] = 0; g_fill[i] = 0; }
}
__global__ void degree_kernel(const void* __restrict__ ei, int E) {
    int e = blockIdx.x * blockDim.x + threadIdx.x;
    if (e < E) {
        int d = load_idx(ei, (size_t)E + e);
        if ((unsigned)d < NN) atomicAdd(&g_cnt[d], 1);
    }
}

// ---------------------------------------------------------------- hierarchical scan
__global__ __launch_bounds__(1024) void scan_partial_kernel() {
    __shared__ int s[1024];
    int tid = threadIdx.x, b = blockIdx.x;
    int i = b * 1024 + tid;
    int v = (i < NN) ? g_cnt[i] : 0;
    if (i < NN) g_inv[i] = 1.0f / fmaxf((float)v, 1.0f);
    s[tid] = v;
    __syncthreads();
#pragma unroll
    for (int off = 1; off < 1024; off <<= 1) {
        int t = (tid >= off) ? s[tid - off] : 0;
        __syncthreads();
        s[tid] += t;
        __syncthreads();
    }
    if (i < NN) g_rowptr[i + 1] = s[tid];
    if (tid == 1023) g_bsum[b] = s[1023];
    if (i == 0) g_rowptr[0] = 0;
}
__global__ void scan_bsum_kernel() {
    __shared__ int s[128];
    int tid = threadIdx.x;
    int v = (tid < NBLK) ? g_bsum[tid] : 0;
    s[tid] = v;
    __syncthreads();
#pragma unroll
    for (int off = 1; off < 128; off <<= 1) {
        int t = (tid >= off) ? s[tid - off] : 0;
        __syncthreads();
        s[tid] += t;
        __syncthreads();
    }
    if (tid < NBLK) g_boff[tid] = s[tid] - v;
}
__global__ __launch_bounds__(1024) void scan_add_kernel() {
    int i = blockIdx.x * 1024 + threadIdx.x;
    if (i < NN) g_rowptr[i + 1] += g_boff[blockIdx.x];
}

// ---------------------------------------------------------------- counting-sort scatter
__global__ void scatter_kernel(const void* __restrict__ ei, int E) {
    int e = blockIdx.x * blockDim.x + threadIdx.x;
    if (e < E) {
        int srcv = load_idx(ei, (size_t)e);
        int d    = load_idx(ei, (size_t)E + e);
        if ((unsigned)d < NN && (unsigned)srcv < NN) {
            int pos = g_rowptr[d] + atomicAdd(&g_fill[d], 1);
            if ((unsigned)pos < EMAX) g_esrc[pos] = srcv;
        }
    }
}

// ---------------------------------------------------------------- aggregate (warp per node, fp16 gather, ILP-8)
__global__ __launch_bounds__(256) void aggregate_kernel() {
    int gtid = blockIdx.x * blockDim.x + threadIdx.x;
    int w = gtid >> 5, lane = gtid & 31;
    if (w >= NN) return;
    int beg = g_rowptr[w], end = g_rowptr[w + 1];
    const __half2* __restrict__ base = (const __half2*)g_h16;

    float2 ac[8];
#pragma unroll
    for (int i = 0; i < 8; i++) ac[i] = make_float2(0.f, 0.f);
    int n = end - beg;
    int nfull = n & ~31;
    int j = beg;
    for (; j < beg + nfull; j += 32) {
        int sidx = g_esrc[j + lane];
#pragma unroll
        for (int t = 0; t < 32; t += 8) {
            int sv[8];
#pragma unroll
            for (int u = 0; u < 8; u++) sv[u] = __shfl_sync(0xffffffffu, sidx, t + u);
            float2 v[8];
#pragma unroll
            for (int u = 0; u < 8; u++) v[u] = __half22float2(base[(size_t)sv[u] * 32 + lane]);
#pragma unroll
            for (int u = 0; u < 8; u++) { ac[u].x += v[u].x; ac[u].y += v[u].y; }
        }
    }
    if (j < end) {
        int jl = j + lane;
        int sidx = (jl < end) ? g_esrc[jl] : 0;
        int m = end - j;
        for (int t = 0; t < m; t++) {
            int sv = __shfl_sync(0xffffffffu, sidx, t);
            float2 v = __half22float2(base[(size_t)sv * 32 + lane]);
            ac[0].x += v.x; ac[0].y += v.y;
        }
    }
    float inv = g_inv[w];
    float2 acc = make_float2(0.f, 0.f);
#pragma unroll
    for (int i = 0; i < 8; i++) { acc.x += ac[i].x; acc.y += ac[i].y; }
    acc.x *= inv; acc.y *= inv;
    *(__half2*)(g_agg16 + (size_t)w * HD + lane * 2) = __floats2half2_rn(acc.x, acc.y);
}

// ================================================================ fp16-split MMA GEMMs
#define A2W 36
#define B2W 72

__device__ __forceinline__ void storeA_planes(__half2* Ah, __half2* Al,
                                              const float4* va, int tid) {
#pragma unroll
    for (int it = 0; it < 4; it++) {
        int idx = tid + it * 256;
        int r = idx >> 4, c4 = idx & 15;
        __half2 h0, l0, h1, l1;
        split2(va[it].x, va[it].y, h0, l0);
        split2(va[it].z, va[it].w, h1, l1);
        __half2* ph = Ah + r * A2W + c4 * 2;
        __half2* pl = Al + r * A2W + c4 * 2;
        *(uint2*)ph = make_uint2(*(uint32_t*)&h0, *(uint32_t*)&h1);
        *(uint2*)pl = make_uint2(*(uint32_t*)&l0, *(uint32_t*)&l1);
    }
}
// copy pre-packed fp16 rows straight into the hi smem plane (no ALU)
__device__ __forceinline__ void copyA_hi(__half2* Ah, const __half* hi,
                                         int row0, int tid) {
#pragma unroll
    for (int it = 0; it < 4; it++) {
        int idx = tid + it * 256;
        int r = idx >> 4, c4 = idx & 15;
        int grow = row0 + r;
        uint2 vh = make_uint2(0u, 0u);
        if (grow < NN) vh = *(const uint2*)(hi + (size_t)grow * 64 + c4 * 4);
        *(uint2*)(Ah + r * A2W + c4 * 2) = vh;
    }
}
// hi-only B stage (fp16-rounded weights; no residual plane)
__device__ __forceinline__ void storeB_hi(__half2* Bh, const float4* vb, int tid) {
    int k2 = tid >> 3, ng = (tid & 7) * 8;
    const float* r0 = (const float*)&vb[0];
    const float* r1 = (const float*)&vb[2];
    __half2 hh[8];
#pragma unroll
    for (int jj = 0; jj < 8; jj++) hh[jj] = __floats2half2_rn(r0[jj], r1[jj]);
    uint4* ph = (uint4*)(Bh + k2 * B2W + ng);
    ph[0] = make_uint4(*(uint32_t*)&hh[0], *(uint32_t*)&hh[1], *(uint32_t*)&hh[2], *(uint32_t*)&hh[3]);
    ph[1] = make_uint4(*(uint32_t*)&hh[4], *(uint32_t*)&hh[5], *(uint32_t*)&hh[6], *(uint32_t*)&hh[7]);
}

// 2-product kstep, A split / B hi-only: (ah+al)*bh — exact A, fp16 weights
__device__ __forceinline__ void mma_kstep16_xsplit(const __half2* Ah, const __half2* Al,
                                                   const __half2* Bh,
                                                   int m0, int n0, int k2b,
                                                   int qrow, int qcol, float acc[4][4]) {
    uint32_t ah[4], al[4];
    int ra = (m0 + qrow) * A2W + k2b + qcol;
    ah[0] = *(const uint32_t*)&Ah[ra];
    ah[1] = *(const uint32_t*)&Ah[ra + 8 * A2W];
    ah[2] = *(const uint32_t*)&Ah[ra + 4];
    ah[3] = *(const uint32_t*)&Ah[ra + 8 * A2W + 4];
    al[0] = *(const uint32_t*)&Al[ra];
    al[1] = *(const uint32_t*)&Al[ra + 8 * A2W];
    al[2] = *(const uint32_t*)&Al[ra + 4];
    al[3] = *(const uint32_t*)&Al[ra + 8 * A2W + 4];
#pragma unroll
    for (int nt = 0; nt < 4; nt++) {
        int nn = n0 + nt * 8;
        int rb = (k2b + qcol) * B2W + nn + qrow;
        uint32_t bh[2];
        bh[0] = *(const uint32_t*)&Bh[rb];
        bh[1] = *(const uint32_t*)&Bh[rb + 4 * B2W];
        mma_f16(acc[nt], ah, bh);
        mma_f16(acc[nt], al, bh);
    }
}
// 1-product kstep: A hi-only × B hi-only (agg16 × W16)
__device__ __forceinline__ void mma_kstep16_hihi(const __half2* Ah,
                                                 const __half2* Bh,
                                                 int m0, int n0, int k2b,
                                                 int qrow, int qcol, float acc[4][4]) {
    uint32_t ah[4];
    int ra = (m0 + qrow) * A2W + k2b + qcol;
    ah[0] = *(const uint32_t*)&Ah[ra];
    ah[1] = *(const uint32_t*)&Ah[ra + 8 * A2W];
    ah[2] = *(const uint32_t*)&Ah[ra + 4];
    ah[3] = *(const uint32_t*)&Ah[ra + 8 * A2W + 4];
#pragma unroll
    for (int nt = 0; nt < 4; nt++) {
        int nn = n0 + nt * 8;
        int rb = (k2b + qcol) * B2W + nn + qrow;
        uint32_t bh[2];
        bh[0] = *(const uint32_t*)&Bh[rb];
        bh[1] = *(const uint32_t*)&Bh[rb + 4 * B2W];
        mma_f16(acc[nt], ah, bh);
    }
}

// ---------------------------------------------------------------- input GEMM: h = x @ Win_fp16 + b_in
__global__ __launch_bounds__(256) void gemm_in_mma(const float* __restrict__ x,
                                                   const float* __restrict__ Win,
                                                   const float* __restrict__ bin) {
    __shared__ __align__(16) __half2 Ah[64 * A2W], Al[64 * A2W];
    __shared__ __align__(16) __half2 Bh[32 * B2W];
    int tid = threadIdx.x;
    int wid = tid >> 5, lane = tid & 31;
    int warpM = wid & 3, warpN = wid >> 2;
    int qrow = lane >> 2, qcol = lane & 3;
    int row0 = blockIdx.x * 64;
    float acc[4][4];
#pragma unroll
    for (int nt = 0; nt < 4; nt++)
#pragma unroll
        for (int i = 0; i < 4; i++) acc[nt][i] = 0.f;

    float4 va[4], vb[4];
    {
        int k2 = tid >> 3, ng = (tid & 7) * 8;
#pragma unroll
        for (int it = 0; it < 4; it++) {
            int idx = tid + it * 256;
            int r = idx >> 4, c4 = idx & 15;
            int grow = row0 + r;
            va[it] = (grow < NN) ? *(const float4*)(x + (size_t)grow * 512 + c4 * 4)
                                 : make_float4(0.f, 0.f, 0.f, 0.f);
        }
        vb[0] = *(const float4*)(Win + (size_t)(2 * k2) * 64 + ng);
        vb[1] = *(const float4*)(Win + (size_t)(2 * k2) * 64 + ng + 4);
        vb[2] = *(const float4*)(Win + (size_t)(2 * k2 + 1) * 64 + ng);
        vb[3] = *(const float4*)(Win + (size_t)(2 * k2 + 1) * 64 + ng + 4);
    }
#pragma unroll 1
    for (int c = 0; c < 8; c++) {
        storeA_planes(Ah, Al, va, tid);
        storeB_hi(Bh, vb, tid);
        __syncthreads();
        if (c < 7) {
            int kc = (c + 1) * 64;
            int k2 = tid >> 3, ng = (tid & 7) * 8;
#pragma unroll
            for (int it = 0; it < 4; it++) {
                int idx = tid + it * 256;
                int r = idx >> 4, c4 = idx & 15;
                int grow = row0 + r;
                va[it] = (grow < NN) ? *(const float4*)(x + (size_t)grow * 512 + kc + c4 * 4)
                                     : make_float4(0.f, 0.f, 0.f, 0.f);
            }
            vb[0] = *(const float4*)(Win + (size_t)(kc + 2 * k2) * 64 + ng);
            vb[1] = *(const float4*)(Win + (size_t)(kc + 2 * k2) * 64 + ng + 4);
            vb[2] = *(const float4*)(Win + (size_t)(kc + 2 * k2 + 1) * 64 + ng);
            vb[3] = *(const float4*)(Win + (size_t)(kc + 2 * k2 + 1) * 64 + ng + 4);
        }
#pragma unroll
        for (int kk = 0; kk < 4; kk++)
            mma_kstep16_xsplit(Ah, Al, Bh, warpM * 16, warpN * 32, kk * 8, qrow, qcol, acc);
        __syncthreads();
    }
#pragma unroll
    for (int nt = 0; nt < 4; nt++) {
        int gc = warpN * 32 + nt * 8 + qcol * 2;
        float2 bv = *(const float2*)(bin + gc);
#pragma unroll
        for (int half = 0; half < 2; half++) {
            int gr = row0 + warpM * 16 + qrow + half * 8;
            if (gr < NN) {
                float2 o;
                o.x = acc[nt][half * 2 + 0] + bv.x;
                o.y = acc[nt][half * 2 + 1] + bv.y;
                *(float2*)(g_h + (size_t)gr * 64 + gc) = o;
                *(__half2*)(g_h16 + (size_t)gr * 64 + gc) = __floats2half2_rn(o.x, o.y);
            }
        }
    }
}

// ---------------------------------------------------------------- layer GEMM:
// h = h + relu(agg16 @ Wl16 + bl + h @ Wr16); chunk0 = 1 product, chunk1 = 2 products
__global__ __launch_bounds__(256) void gemm_layer_mma(const float* __restrict__ Wl,
                                                      const float* __restrict__ Wr,
                                                      const float* __restrict__ bl) {
    __shared__ __align__(16) __half2 Ah[64 * A2W], Al[64 * A2W];
    __shared__ __align__(16) __half2 Bh[32 * B2W];
    int tid = threadIdx.x;
    int wid = tid >> 5, lane = tid & 31;
    int warpM = wid & 3, warpN = wid >> 2;
    int qrow = lane >> 2, qcol = lane & 3;
    int row0 = blockIdx.x * 64;
    float acc[4][4];
#pragma unroll
    for (int nt = 0; nt < 4; nt++)
#pragma unroll
        for (int i = 0; i < 4; i++) acc[nt][i] = 0.f;

    // ---- chunk 0: agg16 (hi) @ Wl16 (hi) — 1 product
    {
        float4 vb[4];
        int k2 = tid >> 3, ng = (tid & 7) * 8;
        vb[0] = *(const float4*)(Wl + (size_t)(2 * k2) * 64 + ng);
        vb[1] = *(const float4*)(Wl + (size_t)(2 * k2) * 64 + ng + 4);
        vb[2] = *(const float4*)(Wl + (size_t)(2 * k2 + 1) * 64 + ng);
        vb[3] = *(const float4*)(Wl + (size_t)(2 * k2 + 1) * 64 + ng + 4);
        copyA_hi(Ah, g_agg16, row0, tid);
        storeB_hi(Bh, vb, tid);
        __syncthreads();
#pragma unroll
        for (int kk = 0; kk < 4; kk++)
            mma_kstep16_hihi(Ah, Bh, warpM * 16, warpN * 32, kk * 8, qrow, qcol, acc);
        __syncthreads();
    }
    // ---- chunk 1: h (hi/lo split) @ Wr16 (hi) — 2 products
    {
        float4 va[4], vb[4];
        int k2 = tid >> 3, ng = (tid & 7) * 8;
#pragma unroll
        for (int it = 0; it < 4; it++) {
            int idx = tid + it * 256;
            int r = idx >> 4, c4 = idx & 15;
            int grow = row0 + r;
            va[it] = (grow < NN) ? *(const float4*)(g_h + (size_t)grow * 64 + c4 * 4)
                                 : make_float4(0.f, 0.f, 0.f, 0.f);
        }
        vb[0] = *(const float4*)(Wr + (size_t)(2 * k2) * 64 + ng);
        vb[1] = *(const float4*)(Wr + (size_t)(2 * k2) * 64 + ng + 4);
        vb[2] = *(const float4*)(Wr + (size_t)(2 * k2 + 1) * 64 + ng);
        vb[3] = *(const float4*)(Wr + (size_t)(2 * k2 + 1) * 64 + ng + 4);
        storeA_planes(Ah, Al, va, tid);
        storeB_hi(Bh, vb, tid);
        __syncthreads();
#pragma unroll
        for (int kk = 0; kk < 4; kk++)
            mma_kstep16_xsplit(Ah, Al, Bh, warpM * 16, warpN * 32, kk * 8, qrow, qcol, acc);
    }
#pragma unroll
    for (int nt = 0; nt < 4; nt++) {
        int gc = warpN * 32 + nt * 8 + qcol * 2;
        float2 bv = *(const float2*)(bl + gc);
#pragma unroll
        for (int half = 0; half < 2; half++) {
            int gr = row0 + warpM * 16 + qrow + half * 8;
            if (gr < NN) {
                float2 old = *(const float2*)(g_h + (size_t)gr * 64 + gc);
                float2 o;
                o.x = old.x + fmaxf(acc[nt][half * 2 + 0] + bv.x, 0.f);
                o.y = old.y + fmaxf(acc[nt][half * 2 + 1] + bv.y, 0.f);
                *(float2*)(g_h + (size_t)gr * 64 + gc) = o;
                *(__half2*)(g_h16 + (size_t)gr * 64 + gc) = __floats2half2_rn(o.x, o.y);
            }
        }
    }
}

// ---------------------------------------------------------------- output GEMM: out = h @ Wout16 + b_out
__global__ __launch_bounds__(256) void gemm_out_mma(const float* __restrict__ Wout,
                                                    const float* __restrict__ bout,
                                                    float* __restrict__ out) {
    __shared__ __align__(16) __half2 Ah[64 * A2W], Al[64 * A2W];
    __shared__ __align__(16) __half2 Bh[32 * B2W];
    int tid = threadIdx.x;
    int wid = tid >> 5, lane = tid & 31;
    int warpM = wid & 3, warpN = wid >> 2;
    int qrow = lane >> 2, qcol = lane & 3;
    int row0 = blockIdx.x * 64;
    int col0 = blockIdx.y * 64;
    float acc[4][4];
#pragma unroll
    for (int nt = 0; nt < 4; nt++)
#pragma unroll
        for (int i = 0; i < 4; i++) acc[nt][i] = 0.f;

    {
        float4 va[4], vb[4];
        int k2 = tid >> 3, ng = (tid & 7) * 8;
#pragma unroll
        for (int it = 0; it < 4; it++) {
            int idx = tid + it * 256;
            int r = idx >> 4, c4 = idx & 15;
            int grow = row0 + r;
            va[it] = (grow < NN) ? *(const float4*)(g_h + (size_t)grow * 64 + c4 * 4)
                                 : make_float4(0.f, 0.f, 0.f, 0.f);
        }
        vb[0] = *(const float4*)(Wout + (size_t)(2 * k2) * 256 + col0 + ng);
        vb[1] = *(const float4*)(Wout + (size_t)(2 * k2) * 256 + col0 + ng + 4);
        vb[2] = *(const float4*)(Wout + (size_t)(2 * k2 + 1) * 256 + col0 + ng);
        vb[3] = *(const float4*)(Wout + (size_t)(2 * k2 + 1) * 256 + col0 + ng + 4);
        storeA_planes(Ah, Al, va, tid);
        storeB_hi(Bh, vb, tid);
    }
    __syncthreads();
#pragma unroll
    for (int kk = 0; kk < 4; kk++)
        mma_kstep16_xsplit(Ah, Al, Bh, warpM * 16, warpN * 32, kk * 8, qrow, qcol, acc);

#pragma unroll
    for (int nt = 0; nt < 4; nt++) {
        int gc = warpN * 32 + nt * 8 + qcol * 2;
        float2 bv = *(const float2*)(bout + col0 + gc);
#pragma unroll
        for (int half = 0; half < 2; half++) {
            int gr = row0 + warpM * 16 + qrow + half * 8;
            if (gr < NN) {
                float2 o;
                o.x = acc[nt][half * 2 + 0] + bv.x;
                o.y = acc[nt][half * 2 + 1] + bv.y;
                *(float2*)(out + (size_t)gr * 256 + col0 + gc) = o;
            }
        }
    }
}

// ---------------------------------------------------------------- launch
extern "C" void kernel_launch(void* const* d_in, const int* in_sizes, int n_in,
                              void* d_out, int out_size) {
    const float* x    = (const float*)d_in[0];
    const void*  ei   = d_in[1];
    const float* Win  = (const float*)d_in[2];
    const float* bin  = (const float*)d_in[3];
    const float* Wl   = (const float*)d_in[4];
    const float* bl   = (const float*)d_in[5];
    const float* Wr   = (const float*)d_in[6];
    const float* Wout = (const float*)d_in[7];
    const float* bout = (const float*)d_in[8];
    float* out = (float*)d_out;
    int E = in_sizes[1] / 2;

    static cudaStream_t s_side = nullptr;
    static cudaEvent_t  e_fork = nullptr, e_join = nullptr;
    if (s_side == nullptr) {
        cudaStreamCreateWithFlags(&s_side, cudaStreamNonBlocking);
        cudaEventCreateWithFlags(&e_fork, cudaEventDisableTiming);
        cudaEventCreateWithFlags(&e_join, cudaEventDisableTiming);
    }

    cudaEventRecord(e_fork, 0);
    cudaStreamWaitEvent(s_side, e_fork, 0);

    // ---- side stream: CSR build chain (edge_index only)
    detect_kernel<<<1, 32, 0, s_side>>>((const int*)ei);
    zero_kernel<<<(NN + 255) / 256, 256, 0, s_side>>>();
    degree_kernel<<<(E + 255) / 256, 256, 0, s_side>>>(ei, E);
    scan_partial_kernel<<<NBLK, 1024, 0, s_side>>>();
    scan_bsum_kernel<<<1, 128, 0, s_side>>>();
    scan_add_kernel<<<NBLK, 1024, 0, s_side>>>();
    scatter_kernel<<<(E + 255) / 256, 256, 0, s_side>>>(ei, E);
    cudaEventRecord(e_join, s_side);

    // ---- main stream: input GEMM — overlaps CSR build
    gemm_in_mma<<<MBLK, 256>>>(x, Win, bin);

    cudaStreamWaitEvent(0, e_join, 0);

    for (int i = 0; i < 4; i++) {
        aggregate_kernel<<<(NN * 32 + 255) / 256, 256>>>();
        gemm_layer_mma<<<MBLK, 256>>>(Wl + i * HD * HD, Wr + i * HD * HD, bl + i * HD);
    }

    gemm_out_mma<<<dim3(MBLK, 4), 256>>>(Wout, bout, out);
}

// round 17
// speedup vs baseline: 1.3901x; 1.0327x over previous
#include <cuda_runtime.h>
#include <cuda_fp16.h>
#include <cstdint>

#define NN   100000
#define HD   64
#define EMAX 3200000
#define NBLK ((NN + 1023) / 1024)   // 98
#define MBLK ((NN + 63) / 64)       // 1563

// ---- scratch (device globals; no allocation allowed) ----
__device__ __align__(16) __half g_hhi[NN * HD];    // h hi plane (12.8 MB) — gather table
__device__ __align__(16) __half g_hlo[NN * HD];    // h lo residual plane (12.8 MB)
__device__ __align__(16) __half g_agg16[NN * HD];  // aggregated neighbors, fp16 (12.8 MB)
__device__ int   g_cnt[NN];
__device__ float g_inv[NN];
__device__ int   g_rowptr[NN + 1];
__device__ int   g_fill[NN];
__device__ int   g_esrc[EMAX];
__device__ int   g_is64;
__device__ int   g_bsum[NBLK];
__device__ int   g_boff[NBLK];

// ---------------------------------------------------------------- fp16 split mma helpers
__device__ __forceinline__ void mma_f16(float* d, const uint32_t* a, const uint32_t* b) {
    asm volatile(
        "mma.sync.aligned.m16n8k16.row.col.f32.f16.f16.f32 "
        "{%0,%1,%2,%3}, {%4,%5,%6,%7}, {%8,%9}, {%0,%1,%2,%3};\n"
        : "+f"(d[0]), "+f"(d[1]), "+f"(d[2]), "+f"(d[3])
        : "r"(a[0]), "r"(a[1]), "r"(a[2]), "r"(a[3]), "r"(b[0]), "r"(b[1]));
}
__device__ __forceinline__ void split2(float a, float b, __half2& hi, __half2& lo) {
    __half ha = __float2half_rn(a), hb = __float2half_rn(b);
    hi = __halves2half2(ha, hb);
    lo = __floats2half2_rn(a - __half2float(ha), b - __half2float(hb));
}

// ---------------------------------------------------------------- dtype probe
__global__ void detect_kernel(const int* __restrict__ ei32) {
    if (threadIdx.x == 0 && blockIdx.x == 0) {
        int nz = 0;
        for (int k = 0; k < 64; k++) nz |= ei32[2 * k + 1];
        g_is64 = (nz == 0) ? 1 : 0;
    }
}
__device__ __forceinline__ int load_idx(const void* ei, size_t pos) {
    if (g_is64) return (int)((const long long*)ei)[pos];
    return ((const int*)ei)[pos];
}

// ---------------------------------------------------------------- zero / degree
__global__ void zero_kernel() {
    int i = blockIdx.x * blockDim.x + threadIdx.x;
    if (i < NN) { g_cnt[i] = 0; g_fill[i] = 0; }
}
__global__ void degree_kernel(const void* __restrict__ ei, int E) {
    int e = blockIdx.x * blockDim.x + threadIdx.x;
    if (e < E) {
        int d = load_idx(ei, (size_t)E + e);
        if ((unsigned)d < NN) atomicAdd(&g_cnt[d], 1);
    }
}

// ---------------------------------------------------------------- hierarchical scan
__global__ __launch_bounds__(1024) void scan_partial_kernel() {
    __shared__ int s[1024];
    int tid = threadIdx.x, b = blockIdx.x;
    int i = b * 1024 + tid;
    int v = (i < NN) ? g_cnt[i] : 0;
    if (i < NN) g_inv[i] = 1.0f / fmaxf((float)v, 1.0f);
    s[tid] = v;
    __syncthreads();
#pragma unroll
    for (int off = 1; off < 1024; off <<= 1) {
        int t = (tid >= off) ? s[tid - off] : 0;
        __syncthreads();
        s[tid] += t;
        __syncthreads();
    }
    if (i < NN) g_rowptr[i + 1] = s[tid];
    if (tid == 1023) g_bsum[b] = s[1023];
    if (i == 0) g_rowptr[0] = 0;
}
__global__ void scan_bsum_kernel() {
    __shared__ int s[128];
    int tid = threadIdx.x;
    int v = (tid < NBLK) ? g_bsum[tid] : 0;
    s[tid] = v;
    __syncthreads();
#pragma unroll
    for (int off = 1; off < 128; off <<= 1) {
        int t = (tid >= off) ? s[tid - off] : 0;
        __syncthreads();
        s[tid] += t;
        __syncthreads();
    }
    if (tid < NBLK) g_boff[tid] = s[tid] - v;
}
__global__ __launch_bounds__(1024) void scan_add_kernel() {
    int i = blockIdx.x * 1024 + threadIdx.x;
    if (i < NN) g_rowptr[i + 1] += g_boff[blockIdx.x];
}

// ---------------------------------------------------------------- counting-sort scatter
__global__ void scatter_kernel(const void* __restrict__ ei, int E) {
    int e = blockIdx.x * blockDim.x + threadIdx.x;
    if (e < E) {
        int srcv = load_idx(ei, (size_t)e);
        int d    = load_idx(ei, (size_t)E + e);
        if ((unsigned)d < NN && (unsigned)srcv < NN) {
            int pos = g_rowptr[d] + atomicAdd(&g_fill[d], 1);
            if ((unsigned)pos < EMAX) g_esrc[pos] = srcv;
        }
    }
}

// ---------------------------------------------------------------- aggregate (warp per node, fp16 gather, ILP-8)
__global__ __launch_bounds__(256) void aggregate_kernel() {
    int gtid = blockIdx.x * blockDim.x + threadIdx.x;
    int w = gtid >> 5, lane = gtid & 31;
    if (w >= NN) return;
    int beg = g_rowptr[w], end = g_rowptr[w + 1];
    const __half2* __restrict__ base = (const __half2*)g_hhi;

    float2 ac[8];
#pragma unroll
    for (int i = 0; i < 8; i++) ac[i] = make_float2(0.f, 0.f);
    int n = end - beg;
    int nfull = n & ~31;
    int j = beg;
    for (; j < beg + nfull; j += 32) {
        int sidx = g_esrc[j + lane];
#pragma unroll
        for (int t = 0; t < 32; t += 8) {
            int sv[8];
#pragma unroll
            for (int u = 0; u < 8; u++) sv[u] = __shfl_sync(0xffffffffu, sidx, t + u);
            float2 v[8];
#pragma unroll
            for (int u = 0; u < 8; u++) v[u] = __half22float2(base[(size_t)sv[u] * 32 + lane]);
#pragma unroll
            for (int u = 0; u < 8; u++) { ac[u].x += v[u].x; ac[u].y += v[u].y; }
        }
    }
    if (j < end) {
        int jl = j + lane;
        int sidx = (jl < end) ? g_esrc[jl] : 0;
        int m = end - j;
        for (int t = 0; t < m; t++) {
            int sv = __shfl_sync(0xffffffffu, sidx, t);
            float2 v = __half22float2(base[(size_t)sv * 32 + lane]);
            ac[0].x += v.x; ac[0].y += v.y;
        }
    }
    float inv = g_inv[w];
    float2 acc = make_float2(0.f, 0.f);
#pragma unroll
    for (int i = 0; i < 8; i++) { acc.x += ac[i].x; acc.y += ac[i].y; }
    acc.x *= inv; acc.y *= inv;
    *(__half2*)(g_agg16 + (size_t)w * HD + lane * 2) = __floats2half2_rn(acc.x, acc.y);
}

// ================================================================ fp16-split MMA GEMMs
#define A2W 36
#define B2W 72

__device__ __forceinline__ void storeA_planes(__half2* Ah, __half2* Al,
                                              const float4* va, int tid) {
#pragma unroll
    for (int it = 0; it < 4; it++) {
        int idx = tid + it * 256;
        int r = idx >> 4, c4 = idx & 15;
        __half2 h0, l0, h1, l1;
        split2(va[it].x, va[it].y, h0, l0);
        split2(va[it].z, va[it].w, h1, l1);
        __half2* ph = Ah + r * A2W + c4 * 2;
        __half2* pl = Al + r * A2W + c4 * 2;
        *(uint2*)ph = make_uint2(*(uint32_t*)&h0, *(uint32_t*)&h1);
        *(uint2*)pl = make_uint2(*(uint32_t*)&l0, *(uint32_t*)&l1);
    }
}
// copy pre-packed fp16 rows straight into one smem plane (no ALU)
__device__ __forceinline__ void copyA_hi(__half2* Ah, const __half* hi,
                                         int row0, int tid) {
#pragma unroll
    for (int it = 0; it < 4; it++) {
        int idx = tid + it * 256;
        int r = idx >> 4, c4 = idx & 15;
        int grow = row0 + r;
        uint2 vh = make_uint2(0u, 0u);
        if (grow < NN) vh = *(const uint2*)(hi + (size_t)grow * 64 + c4 * 4);
        *(uint2*)(Ah + r * A2W + c4 * 2) = vh;
    }
}
// copy both pre-split planes (no ALU)
__device__ __forceinline__ void copyA_planes(__half2* Ah, __half2* Al,
                                             const __half* hi, const __half* lo,
                                             int row0, int tid) {
#pragma unroll
    for (int it = 0; it < 4; it++) {
        int idx = tid + it * 256;
        int r = idx >> 4, c4 = idx & 15;
        int grow = row0 + r;
        uint2 vh = make_uint2(0u, 0u), vl = make_uint2(0u, 0u);
        if (grow < NN) {
            vh = *(const uint2*)(hi + (size_t)grow * 64 + c4 * 4);
            vl = *(const uint2*)(lo + (size_t)grow * 64 + c4 * 4);
        }
        *(uint2*)(Ah + r * A2W + c4 * 2) = vh;
        *(uint2*)(Al + r * A2W + c4 * 2) = vl;
    }
}
// hi-only B stage (fp16-rounded weights)
__device__ __forceinline__ void storeB_hi(__half2* Bh, const float4* vb, int tid) {
    int k2 = tid >> 3, ng = (tid & 7) * 8;
    const float* r0 = (const float*)&vb[0];
    const float* r1 = (const float*)&vb[2];
    __half2 hh[8];
#pragma unroll
    for (int jj = 0; jj < 8; jj++) hh[jj] = __floats2half2_rn(r0[jj], r1[jj]);
    uint4* ph = (uint4*)(Bh + k2 * B2W + ng);
    ph[0] = make_uint4(*(uint32_t*)&hh[0], *(uint32_t*)&hh[1], *(uint32_t*)&hh[2], *(uint32_t*)&hh[3]);
    ph[1] = make_uint4(*(uint32_t*)&hh[4], *(uint32_t*)&hh[5], *(uint32_t*)&hh[6], *(uint32_t*)&hh[7]);
}

// 2-product kstep, A split / B hi-only: (ah+al)*bh
__device__ __forceinline__ void mma_kstep16_xsplit(const __half2* Ah, const __half2* Al,
                                                   const __half2* Bh,
                                                   int m0, int n0, int k2b,
                                                   int qrow, int qcol, float acc[4][4]) {
    uint32_t ah[4], al[4];
    int ra = (m0 + qrow) * A2W + k2b + qcol;
    ah[0] = *(const uint32_t*)&Ah[ra];
    ah[1] = *(const uint32_t*)&Ah[ra + 8 * A2W];
    ah[2] = *(const uint32_t*)&Ah[ra + 4];
    ah[3] = *(const uint32_t*)&Ah[ra + 8 * A2W + 4];
    al[0] = *(const uint32_t*)&Al[ra];
    al[1] = *(const uint32_t*)&Al[ra + 8 * A2W];
    al[2] = *(const uint32_t*)&Al[ra + 4];
    al[3] = *(const uint32_t*)&Al[ra + 8 * A2W + 4];
#pragma unroll
    for (int nt = 0; nt < 4; nt++) {
        int nn = n0 + nt * 8;
        int rb = (k2b + qcol) * B2W + nn + qrow;
        uint32_t bh[2];
        bh[0] = *(const uint32_t*)&Bh[rb];
        bh[1] = *(const uint32_t*)&Bh[rb + 4 * B2W];
        mma_f16(acc[nt], ah, bh);
        mma_f16(acc[nt], al, bh);
    }
}
// 1-product kstep: A hi-only × B hi-only
__device__ __forceinline__ void mma_kstep16_hihi(const __half2* Ah,
                                                 const __half2* Bh,
                                                 int m0, int n0, int k2b,
                                                 int qrow, int qcol, float acc[4][4]) {
    uint32_t ah[4];
    int ra = (m0 + qrow) * A2W + k2b + qcol;
    ah[0] = *(const uint32_t*)&Ah[ra];
    ah[1] = *(const uint32_t*)&Ah[ra + 8 * A2W];
    ah[2] = *(const uint32_t*)&Ah[ra + 4];
    ah[3] = *(const uint32_t*)&Ah[ra + 8 * A2W + 4];
#pragma unroll
    for (int nt = 0; nt < 4; nt++) {
        int nn = n0 + nt * 8;
        int rb = (k2b + qcol) * B2W + nn + qrow;
        uint32_t bh[2];
        bh[0] = *(const uint32_t*)&Bh[rb];
        bh[1] = *(const uint32_t*)&Bh[rb + 4 * B2W];
        mma_f16(acc[nt], ah, bh);
    }
}

// ---------------------------------------------------------------- input GEMM: h = x @ Win_fp16 + b_in
__global__ __launch_bounds__(256) void gemm_in_mma(const float* __restrict__ x,
                                                   const float* __restrict__ Win,
                                                   const float* __restrict__ bin) {
    __shared__ __align__(16) __half2 Ah[64 * A2W], Al[64 * A2W];
    __shared__ __align__(16) __half2 Bh[32 * B2W];
    int tid = threadIdx.x;
    int wid = tid >> 5, lane = tid & 31;
    int warpM = wid & 3, warpN = wid >> 2;
    int qrow = lane >> 2, qcol = lane & 3;
    int row0 = blockIdx.x * 64;
    float acc[4][4];
#pragma unroll
    for (int nt = 0; nt < 4; nt++)
#pragma unroll
        for (int i = 0; i < 4; i++) acc[nt][i] = 0.f;

    float4 va[4], vb[4];
    {
        int k2 = tid >> 3, ng = (tid & 7) * 8;
#pragma unroll
        for (int it = 0; it < 4; it++) {
            int idx = tid + it * 256;
            int r = idx >> 4, c4 = idx & 15;
            int grow = row0 + r;
            va[it] = (grow < NN) ? *(const float4*)(x + (size_t)grow * 512 + c4 * 4)
                                 : make_float4(0.f, 0.f, 0.f, 0.f);
        }
        vb[0] = *(const float4*)(Win + (size_t)(2 * k2) * 64 + ng);
        vb[1] = *(const float4*)(Win + (size_t)(2 * k2) * 64 + ng + 4);
        vb[2] = *(const float4*)(Win + (size_t)(2 * k2 + 1) * 64 + ng);
        vb[3] = *(const float4*)(Win + (size_t)(2 * k2 + 1) * 64 + ng + 4);
    }
#pragma unroll 1
    for (int c = 0; c < 8; c++) {
        storeA_planes(Ah, Al, va, tid);
        storeB_hi(Bh, vb, tid);
        __syncthreads();
        if (c < 7) {
            int kc = (c + 1) * 64;
            int k2 = tid >> 3, ng = (tid & 7) * 8;
#pragma unroll
            for (int it = 0; it < 4; it++) {
                int idx = tid + it * 256;
                int r = idx >> 4, c4 = idx & 15;
                int grow = row0 + r;
                va[it] = (grow < NN) ? *(const float4*)(x + (size_t)grow * 512 + kc + c4 * 4)
                                     : make_float4(0.f, 0.f, 0.f, 0.f);
            }
            vb[0] = *(const float4*)(Win + (size_t)(kc + 2 * k2) * 64 + ng);
            vb[1] = *(const float4*)(Win + (size_t)(kc + 2 * k2) * 64 + ng + 4);
            vb[2] = *(const float4*)(Win + (size_t)(kc + 2 * k2 + 1) * 64 + ng);
            vb[3] = *(const float4*)(Win + (size_t)(kc + 2 * k2 + 1) * 64 + ng + 4);
        }
#pragma unroll
        for (int kk = 0; kk < 4; kk++)
            mma_kstep16_xsplit(Ah, Al, Bh, warpM * 16, warpN * 32, kk * 8, qrow, qcol, acc);
        __syncthreads();
    }
#pragma unroll
    for (int nt = 0; nt < 4; nt++) {
        int gc = warpN * 32 + nt * 8 + qcol * 2;
        float2 bv = *(const float2*)(bin + gc);
#pragma unroll
        for (int half = 0; half < 2; half++) {
            int gr = row0 + warpM * 16 + qrow + half * 8;
            if (gr < NN) {
                float ox = acc[nt][half * 2 + 0] + bv.x;
                float oy = acc[nt][half * 2 + 1] + bv.y;
                __half2 hi, lo;
                split2(ox, oy, hi, lo);
                *(__half2*)(g_hhi + (size_t)gr * 64 + gc) = hi;
                *(__half2*)(g_hlo + (size_t)gr * 64 + gc) = lo;
            }
        }
    }
}

// ---------------------------------------------------------------- layer GEMM:
// h = h + relu(agg16 @ Wl16 + bl + h @ Wr16); h kept as hi/lo fp16 planes
__global__ __launch_bounds__(256) void gemm_layer_mma(const float* __restrict__ Wl,
                                                      const float* __restrict__ Wr,
                                                      const float* __restrict__ bl) {
    __shared__ __align__(16) __half2 Ah[64 * A2W], Al[64 * A2W];
    __shared__ __align__(16) __half2 Bh[32 * B2W];
    int tid = threadIdx.x;
    int wid = tid >> 5, lane = tid & 31;
    int warpM = wid & 3, warpN = wid >> 2;
    int qrow = lane >> 2, qcol = lane & 3;
    int row0 = blockIdx.x * 64;
    float acc[4][4];
#pragma unroll
    for (int nt = 0; nt < 4; nt++)
#pragma unroll
        for (int i = 0; i < 4; i++) acc[nt][i] = 0.f;

    // ---- chunk 0: agg16 (hi) @ Wl16 (hi) — 1 product
    {
        float4 vb[4];
        int k2 = tid >> 3, ng = (tid & 7) * 8;
        vb[0] = *(const float4*)(Wl + (size_t)(2 * k2) * 64 + ng);
        vb[1] = *(const float4*)(Wl + (size_t)(2 * k2) * 64 + ng + 4);
        vb[2] = *(const float4*)(Wl + (size_t)(2 * k2 + 1) * 64 + ng);
        vb[3] = *(const float4*)(Wl + (size_t)(2 * k2 + 1) * 64 + ng + 4);
        copyA_hi(Ah, g_agg16, row0, tid);
        storeB_hi(Bh, vb, tid);
        __syncthreads();
#pragma unroll
        for (int kk = 0; kk < 4; kk++)
            mma_kstep16_hihi(Ah, Bh, warpM * 16, warpN * 32, kk * 8, qrow, qcol, acc);
        __syncthreads();
    }
    // ---- chunk 1: h (pre-split hi/lo planes, pure copy) @ Wr16 — 2 products
    {
        float4 vb[4];
        int k2 = tid >> 3, ng = (tid & 7) * 8;
        vb[0] = *(const float4*)(Wr + (size_t)(2 * k2) * 64 + ng);
        vb[1] = *(const float4*)(Wr + (size_t)(2 * k2) * 64 + ng + 4);
        vb[2] = *(const float4*)(Wr + (size_t)(2 * k2 + 1) * 64 + ng);
        vb[3] = *(const float4*)(Wr + (size_t)(2 * k2 + 1) * 64 + ng + 4);
        copyA_planes(Ah, Al, g_hhi, g_hlo, row0, tid);
        storeB_hi(Bh, vb, tid);
        __syncthreads();
#pragma unroll
        for (int kk = 0; kk < 4; kk++)
            mma_kstep16_xsplit(Ah, Al, Bh, warpM * 16, warpN * 32, kk * 8, qrow, qcol, acc);
    }
    // ---- epilogue: h += relu(acc + bl); old h = hi+lo (read from smem planes)
#pragma unroll
    for (int nt = 0; nt < 4; nt++) {
        int gc = warpN * 32 + nt * 8 + qcol * 2;
        float2 bv = *(const float2*)(bl + gc);
#pragma unroll
        for (int half = 0; half < 2; half++) {
            int lr = warpM * 16 + qrow + half * 8;
            int gr = row0 + lr;
            if (gr < NN) {
                float2 oh = __half22float2(Ah[lr * A2W + gc / 2]);
                float2 ol = __half22float2(Al[lr * A2W + gc / 2]);
                float ox = (oh.x + ol.x) + fmaxf(acc[nt][half * 2 + 0] + bv.x, 0.f);
                float oy = (oh.y + ol.y) + fmaxf(acc[nt][half * 2 + 1] + bv.y, 0.f);
                __half2 hi, lo;
                split2(ox, oy, hi, lo);
                *(__half2*)(g_hhi + (size_t)gr * 64 + gc) = hi;
                *(__half2*)(g_hlo + (size_t)gr * 64 + gc) = lo;
            }
        }
    }
}

// ---------------------------------------------------------------- output GEMM: out = h @ Wout16 + b_out
__global__ __launch_bounds__(256) void gemm_out_mma(const float* __restrict__ Wout,
                                                    const float* __restrict__ bout,
                                                    float* __restrict__ out) {
    __shared__ __align__(16) __half2 Ah[64 * A2W], Al[64 * A2W];
    __shared__ __align__(16) __half2 Bh[32 * B2W];
    int tid = threadIdx.x;
    int wid = tid >> 5, lane = tid & 31;
    int warpM = wid & 3, warpN = wid >> 2;
    int qrow = lane >> 2, qcol = lane & 3;
    int row0 = blockIdx.x * 64;
    int col0 = blockIdx.y * 64;
    float acc[4][4];
#pragma unroll
    for (int nt = 0; nt < 4; nt++)
#pragma unroll
        for (int i = 0; i < 4; i++) acc[nt][i] = 0.f;

    {
        float4 vb[4];
        int k2 = tid >> 3, ng = (tid & 7) * 8;
        vb[0] = *(const float4*)(Wout + (size_t)(2 * k2) * 256 + col0 + ng);
        vb[1] = *(const float4*)(Wout + (size_t)(2 * k2) * 256 + col0 + ng + 4);
        vb[2] = *(const float4*)(Wout + (size_t)(2 * k2 + 1) * 256 + col0 + ng);
        vb[3] = *(const float4*)(Wout + (size_t)(2 * k2 + 1) * 256 + col0 + ng + 4);
        copyA_planes(Ah, Al, g_hhi, g_hlo, row0, tid);
        storeB_hi(Bh, vb, tid);
    }
    __syncthreads();
#pragma unroll
    for (int kk = 0; kk < 4; kk++)
        mma_kstep16_xsplit(Ah, Al, Bh, warpM * 16, warpN * 32, kk * 8, qrow, qcol, acc);

#pragma unroll
    for (int nt = 0; nt < 4; nt++) {
        int gc = warpN * 32 + nt * 8 + qcol * 2;
        float2 bv = *(const float2*)(bout + col0 + gc);
#pragma unroll
        for (int half = 0; half < 2; half++) {
            int gr = row0 + warpM * 16 + qrow + half * 8;
            if (gr < NN) {
                float2 o;
                o.x = acc[nt][half * 2 + 0] + bv.x;
                o.y = acc[nt][half * 2 + 1] + bv.y;
                *(float2*)(out + (size_t)gr * 256 + col0 + gc) = o;
            }
        }
    }
}

// ---------------------------------------------------------------- launch
extern "C" void kernel_launch(void* const* d_in, const int* in_sizes, int n_in,
                              void* d_out, int out_size) {
    const float* x    = (const float*)d_in[0];
    const void*  ei   = d_in[1];
    const float* Win  = (const float*)d_in[2];
    const float* bin  = (const float*)d_in[3];
    const float* Wl   = (const float*)d_in[4];
    const float* bl   = (const float*)d_in[5];
    const float* Wr   = (const float*)d_in[6];
    const float* Wout = (const float*)d_in[7];
    const float* bout = (const float*)d_in[8];
    float* out = (float*)d_out;
    int E = in_sizes[1] / 2;

    static cudaStream_t s_side = nullptr;
    static cudaEvent_t  e_fork = nullptr, e_join = nullptr;
    if (s_side == nullptr) {
        cudaStreamCreateWithFlags(&s_side, cudaStreamNonBlocking);
        cudaEventCreateWithFlags(&e_fork, cudaEventDisableTiming);
        cudaEventCreateWithFlags(&e_join, cudaEventDisableTiming);
    }

    cudaEventRecord(e_fork, 0);
    cudaStreamWaitEvent(s_side, e_fork, 0);

    // ---- side stream: CSR build chain (edge_index only)
    detect_kernel<<<1, 32, 0, s_side>>>((const int*)ei);
    zero_kernel<<<(NN + 255) / 256, 256, 0, s_side>>>();
    degree_kernel<<<(E + 255) / 256, 256, 0, s_side>>>(ei, E);
    scan_partial_kernel<<<NBLK, 1024, 0, s_side>>>();
    scan_bsum_kernel<<<1, 128, 0, s_side>>>();
    scan_add_kernel<<<NBLK, 1024, 0, s_side>>>();
    scatter_kernel<<<(E + 255) / 256, 256, 0, s_side>>>(ei, E);
    cudaEventRecord(e_join, s_side);

    // ---- main stream: input GEMM — overlaps CSR build
    gemm_in_mma<<<MBLK, 256>>>(x, Win, bin);

    cudaStreamWaitEvent(0, e_join, 0);

    for (int i = 0; i < 4; i++) {
        aggregate_kernel<<<(NN * 32 + 255) / 256, 256>>>();
        gemm_layer_mma<<<MBLK, 256>>>(Wl + i * HD * HD, Wr + i * HD * HD, bl + i * HD);
    }

    gemm_out_mma<<<dim3(MBLK, 4), 256>>>(Wout, bout, out);
}